// round 14
// baseline (speedup 1.0000x reference)
#include <cuda_runtime.h>
#include <cuda_fp16.h>
#include <cstdint>
#include <cstddef>

// ---------------------------------------------------------------------------
// Problem constants (MambaVisionMixer, B=4, L=2048)
// ---------------------------------------------------------------------------
#define B_SZ    4
#define LSEQ    2048
#define DMODEL  1024
#define DINNER  2048
#define DHALF   1024
#define DSTATE  16
#define DTRANK  64
#define XDBL_N  96
#define MROWS   (B_SZ*LSEQ)   // 8192
#define NCHUNK  32
#define LCHUNK  (LSEQ/NCHUNK) // 64
#define KSPLIT  4

typedef __half h16;

// ---------------------------------------------------------------------------
// Device scratch (static __device__ arrays — no allocations)
// ---------------------------------------------------------------------------
__device__ h16   g_xzh [(size_t)MROWS * DINNER];    // xz fp16  (32 MB)
__device__ float g_xdbl [(size_t)MROWS * XDBL_N];   // 3 MB
__device__ float g_xp  [(size_t)KSPLIT * MROWS * XDBL_N];  // split-K partials 12 MB
__device__ float g_delta[(size_t)MROWS * DHALF];    // 32 MB

__device__ float g_q [(size_t)B_SZ * NCHUNK * DSTATE * DHALF];  // 8 MB
__device__ float g_hs[(size_t)B_SZ * NCHUNK * DSTATE * DHALF];  // 8 MB
__device__ float g_S [(size_t)B_SZ * NCHUNK * DHALF];           // 512 KB

__device__ h16 g_a1h[(size_t)MROWS * DMODEL];      // x (fp16 rn)
__device__ h16 g_b1h[(size_t)DINNER * DMODEL];     // W_in^T  [2048,1024]
__device__ h16 g_xsh[(size_t)MROWS * DHALF];       // xs hi
__device__ h16 g_xsl[(size_t)MROWS * DHALF];       // xs lo (xdbl path only)
__device__ h16 g_bxh[(size_t)XDBL_N * DHALF];      // W_xdbl^T [96,1024]
__device__ h16 g_dth[(size_t)MROWS * DTRANK];      // dt_low hi [8192,64]
__device__ h16 g_dtl[(size_t)MROWS * DTRANK];
__device__ h16 g_bdh[(size_t)DHALF * DTRANK];      // W_dt^T [1024,64]
__device__ h16 g_bdl[(size_t)DHALF * DTRANK];
__device__ h16 g_ch [(size_t)MROWS * DINNER];      // [y|z] (fp16 rn) [8192,2048]
__device__ h16 g_b2h[(size_t)DMODEL * DINNER];     // W_out^T [1024,2048]

// ---------------------------------------------------------------------------
// Helpers (sm_80-era ISA only: compiles at compute_103 non-'a' target)
// ---------------------------------------------------------------------------
__device__ __forceinline__ uint32_t smem_u32(const void* p) {
    uint32_t r;
    asm("{ .reg .u64 t; cvta.to.shared.u64 t, %1; cvt.u32.u64 %0, t; }"
        : "=r"(r) : "l"(p));
    return r;
}

#define CP16(dst, src) \
    asm volatile("cp.async.cg.shared.global [%0], [%1], 16;" \
        :: "r"(dst), "l"(src) : "memory")
#define CP16Z(dst, src, sz) \
    asm volatile("cp.async.cg.shared.global [%0], [%1], 16, %2;" \
        :: "r"(dst), "l"(src), "r"(sz) : "memory")
#define CP_COMMIT() asm volatile("cp.async.commit_group;" ::: "memory")
#define CP_WAIT2()  asm volatile("cp.async.wait_group 2;" ::: "memory")

__device__ __forceinline__ void ldsm4(uint32_t* r, uint32_t addr) {
    asm volatile("ldmatrix.sync.aligned.m8n8.x4.shared.b16 {%0,%1,%2,%3}, [%4];"
        : "=r"(r[0]), "=r"(r[1]), "=r"(r[2]), "=r"(r[3]) : "r"(addr));
}

__device__ __forceinline__ void mma16816(float* d, const uint32_t* a,
                                         const uint32_t* b) {
    asm volatile(
        "mma.sync.aligned.m16n8k16.row.col.f32.f16.f16.f32 "
        "{%0,%1,%2,%3}, {%4,%5,%6,%7}, {%8,%9}, {%0,%1,%2,%3};"
        : "+f"(d[0]), "+f"(d[1]), "+f"(d[2]), "+f"(d[3])
        : "r"(a[0]), "r"(a[1]), "r"(a[2]), "r"(a[3]), "r"(b[0]), "r"(b[1]));
}

__device__ __forceinline__ float softplus_f(float x) {
    return fmaxf(x, 0.0f) + log1pf(expf(-fabsf(x)));
}
__device__ __forceinline__ float silu_f(float x) {
    return x / (1.0f + expf(-x));
}
__device__ __forceinline__ void split_h16(float v, h16& h, h16& l) {
    h = __float2half_rn(v);
    l = __float2half_rn(v - __half2float(h));
}

// ---------------------------------------------------------------------------
// Tensor-core GEMM (mma.sync fp16, fp32 accum), extended-K streams.
//   C[M,N] = A[M,K] @ B^T   (B stored [N,K] row-major, row stride = lda)
//   NSTREAM==1: (Ahi,Bhi)
//   NSTREAM==2: (Ahi,Bhi), (Alo,Bhi)
//   NSTREAM==3: (Ahi,Bhi), (Ahi,Blo), (Alo,Bhi)
//   Split-K: blockIdx.z = k-split index; A/B advance kz*K along K; output
//   goes to partial slab kz (gridDim.y*BM rows x N).  K = per-split size.
//   CTA BMx128, 8 warps (2x4), warp tile (BM/2)x32, BK=64,
//   3-stage cp.async pipeline.  H16OUT: write C as fp16 rn.
//   DTSPLIT: additionally write fp16 hi/lo of cols [0,64) to dth/dtl.
// ---------------------------------------------------------------------------
template <int BM, int NSTREAM, bool SOFTPLUS, bool HASBIAS, bool NCHK,
          bool DTSPLIT, bool H16OUT>
__global__ __launch_bounds__(256, 2)
void gemm_mma(const h16* __restrict__ Ahi, const h16* __restrict__ Alo,
              const h16* __restrict__ Bhi, const h16* __restrict__ Blo,
              const float* __restrict__ bias, float bias_scale,
              void* __restrict__ Cout, int N, int K, int lda, int Brows,
              h16* __restrict__ dth, h16* __restrict__ dtl)
{
    constexpr int MI     = BM / 32;
    constexpr int ABYTES = BM * 128;
    constexpr int STAGE  = ABYTES + 128 * 128;
    extern __shared__ char dsm[];
    const uint32_t base = (smem_u32(dsm) + 1023u) & ~1023u;

    const int tid    = threadIdx.x;
    const int rowBlk = blockIdx.y * BM;
    const int colBlk = blockIdx.x * 128;
    const int kz     = blockIdx.z;
    const size_t kzC = (size_t)kz * gridDim.y * BM * N;   // partial slab offset
    Ahi += (size_t)kz * K;
    if (NSTREAM >= 2) Alo += (size_t)kz * K;
    Bhi += (size_t)kz * K;
    if (NSTREAM == 3) Blo += (size_t)kz * K;

    const int wid    = tid >> 5;
    const int lane   = tid & 31;
    const int warp_m = wid >> 2;
    const int warp_n = wid & 3;
    const int mat    = lane >> 3;
    const int rin    = lane & 7;

    const int KC     = K / 64;
    const int CHUNKS = NSTREAM * KC;

    uint32_t offA[MI][4], offB[2][4];
    #pragma unroll
    for (int mi = 0; mi < MI; mi++)
        #pragma unroll
        for (int j = 0; j < 4; j++) {
            int row = warp_m * (BM / 2) + mi * 16 + (mat & 1) * 8 + rin;
            int c   = 2 * j + (mat >> 1);
            offA[mi][j] = row * 128 + ((c ^ (row & 7)) << 4);
        }
    #pragma unroll
    for (int bi = 0; bi < 2; bi++)
        #pragma unroll
        for (int j = 0; j < 4; j++) {
            int row = warp_n * 32 + bi * 16 + (mat >> 1) * 8 + rin;
            int c   = 2 * j + (mat & 1);
            offB[bi][j] = ABYTES + row * 128 + ((c ^ (row & 7)) << 4);
        }

    float acc[MI][4][4];
    #pragma unroll
    for (int i = 0; i < MI; i++)
        #pragma unroll
        for (int j = 0; j < 4; j++)
            #pragma unroll
            for (int q = 0; q < 4; q++) acc[i][j][q] = 0.0f;

    auto load_stage = [&](int s, int c) {
        int stream;
        if (NSTREAM == 1)      stream = 0;
        else if (NSTREAM == 2) stream = (c >= KC) ? 1 : 0;
        else                   stream = (c >= 2 * KC) ? 2 : ((c >= KC) ? 1 : 0);
        int k0 = (c - stream * KC) * 64;
        const h16* Ap = Ahi;
        const h16* Bp = Bhi;
        if (NSTREAM == 2) {
            if (stream == 1) Ap = Alo;
        } else if (NSTREAM == 3) {
            if (stream == 2) Ap = Alo;
            else if (stream == 1) Bp = Blo;
        }
        uint32_t as_ = base + s * STAGE;
        uint32_t bs_ = as_ + ABYTES;
        #pragma unroll
        for (int t = 0; t < BM / 32; t++) {
            int idx = tid + t * 256;
            int r = idx >> 3, cc = idx & 7;
            uint32_t dst = as_ + r * 128 + ((cc ^ (r & 7)) << 4);
            const char* src =
                (const char*)(Ap + (size_t)(rowBlk + r) * lda + k0) + cc * 16;
            CP16(dst, src);
        }
        #pragma unroll
        for (int t = 0; t < 4; t++) {
            int idx = tid + t * 256;
            int r = idx >> 3, cc = idx & 7;
            uint32_t dst = bs_ + r * 128 + ((cc ^ (r & 7)) << 4);
            if (NCHK) {
                int br = colBlk + r;
                int ok = (br < Brows);
                const char* src =
                    (const char*)(Bp + (size_t)(ok ? br : 0) * lda + k0) + cc * 16;
                CP16Z(dst, src, ok ? 16u : 0u);
            } else {
                const char* src =
                    (const char*)(Bp + (size_t)(colBlk + r) * lda + k0) + cc * 16;
                CP16(dst, src);
            }
        }
    };

    #pragma unroll
    for (int s = 0; s < 3; s++) { load_stage(s, s); CP_COMMIT(); }

    int slot = 0;
    #pragma unroll 1
    for (int i = 0; i < CHUNKS; i++) {
        CP_WAIT2();
        __syncthreads();
        const uint32_t sb = base + slot * STAGE;
        #pragma unroll
        for (int j = 0; j < 4; j++) {
            uint32_t Af[MI][4];
            #pragma unroll
            for (int mi = 0; mi < MI; mi++) ldsm4(Af[mi], sb + offA[mi][j]);
            uint32_t Bf[4][2];
            #pragma unroll
            for (int bi = 0; bi < 2; bi++) {
                uint32_t r[4];
                ldsm4(r, sb + offB[bi][j]);
                Bf[bi * 2 + 0][0] = r[0]; Bf[bi * 2 + 0][1] = r[1];
                Bf[bi * 2 + 1][0] = r[2]; Bf[bi * 2 + 1][1] = r[3];
            }
            #pragma unroll
            for (int mi = 0; mi < MI; mi++)
                #pragma unroll
                for (int ni = 0; ni < 4; ni++)
                    mma16816(acc[mi][ni], Af[mi], Bf[ni]);
        }
        __syncthreads();
        if (i + 3 < CHUNKS) load_stage(slot, i + 3);
        CP_COMMIT();
        slot = (slot == 2) ? 0 : slot + 1;
    }

    // epilogue
    const int mrow = rowBlk + warp_m * (BM / 2) + (lane >> 2);
    const int ncol = colBlk + warp_n * 32 + (lane & 3) * 2;
    #pragma unroll
    for (int mi = 0; mi < MI; mi++) {
        #pragma unroll
        for (int ni = 0; ni < 4; ni++) {
            int n0 = ncol + ni * 8;
            if (NCHK && n0 >= Brows) continue;
            float v0 = acc[mi][ni][0], v1 = acc[mi][ni][1];
            float v2 = acc[mi][ni][2], v3 = acc[mi][ni][3];
            if (HASBIAS) {
                float b0 = bias_scale * __ldg(bias + n0);
                float b1 = bias_scale * __ldg(bias + n0 + 1);
                v0 += b0; v1 += b1; v2 += b0; v3 += b1;
            }
            if (SOFTPLUS) {
                v0 = softplus_f(v0); v1 = softplus_f(v1);
                v2 = softplus_f(v2); v3 = softplus_f(v3);
            }
            size_t r0 = kzC + (size_t)(mrow + mi * 16) * N + n0;
            size_t r1 = kzC + (size_t)(mrow + mi * 16 + 8) * N + n0;
            if (H16OUT) {
                h16* Ch = reinterpret_cast<h16*>(Cout);
                *reinterpret_cast<__half2*>(Ch + r0) =
                    __half2(__float2half_rn(v0), __float2half_rn(v1));
                *reinterpret_cast<__half2*>(Ch + r1) =
                    __half2(__float2half_rn(v2), __float2half_rn(v3));
            } else {
                float* Cf = reinterpret_cast<float*>(Cout);
                *reinterpret_cast<float2*>(Cf + r0) = make_float2(v0, v1);
                *reinterpret_cast<float2*>(Cf + r1) = make_float2(v2, v3);
            }
            if (DTSPLIT && n0 < DTRANK) {
                h16 hh, ll;
                size_t d0 = (size_t)(mrow + mi * 16) * DTRANK + n0;
                size_t d1 = (size_t)(mrow + mi * 16 + 8) * DTRANK + n0;
                split_h16(v0, hh, ll); dth[d0] = hh;     dtl[d0] = ll;
                split_h16(v1, hh, ll); dth[d0 + 1] = hh; dtl[d0 + 1] = ll;
                split_h16(v2, hh, ll); dth[d1] = hh;     dtl[d1] = ll;
                split_h16(v3, hh, ll); dth[d1 + 1] = hh; dtl[d1 + 1] = ll;
            }
        }
    }
}

// ---------------------------------------------------------------------------
// Split-K reduce for xdbl: sum 4 partial slabs -> xdbl fp32; cols [0,64)
// additionally emit fp16 hi/lo (dth/dtl).  One float4 per thread.
// ---------------------------------------------------------------------------
__global__ __launch_bounds__(256)
void reduce_xdbl_kernel(const float* __restrict__ part,
                        float* __restrict__ xdbl,
                        h16* __restrict__ dth, h16* __restrict__ dtl)
{
    const int NQ = MROWS * XDBL_N / 4;           // 196608 quads
    int i = blockIdx.x * 256 + threadIdx.x;
    const float4* p4 = reinterpret_cast<const float4*>(part);
    float4 a = p4[i], b = p4[i + NQ], c = p4[i + 2 * NQ], d = p4[i + 3 * NQ];
    float4 s = make_float4((a.x + b.x) + (c.x + d.x), (a.y + b.y) + (c.y + d.y),
                           (a.z + b.z) + (c.z + d.z), (a.w + b.w) + (c.w + d.w));
    reinterpret_cast<float4*>(xdbl)[i] = s;
    int e = i * 4;
    int r = e / XDBL_N, col = e % XDBL_N;        // quads never straddle col 64
    if (col < DTRANK) {
        size_t o = (size_t)r * DTRANK + col;
        h16 h, l;
        split_h16(s.x, h, l); dth[o] = h;     dtl[o] = l;
        split_h16(s.y, h, l); dth[o + 1] = h; dtl[o + 1] = l;
        split_h16(s.z, h, l); dth[o + 2] = h; dtl[o + 2] = l;
        split_h16(s.w, h, l); dth[o + 3] = h; dtl[o + 3] = l;
    }
}

// ---------------------------------------------------------------------------
// Combined prep — ONE launch: 4 weight transposes(+split) AND x -> fp16.
// ---------------------------------------------------------------------------
__global__ __launch_bounds__(256)
void prep_kernel(const float* __restrict__ W_in,
                 const float* __restrict__ W_xdbl,
                 const float* __restrict__ W_dt,
                 const float* __restrict__ W_out,
                 const float* __restrict__ x,
                 h16* __restrict__ b1h, h16* __restrict__ bxh,
                 h16* __restrict__ bdh, h16* __restrict__ bdl,
                 h16* __restrict__ b2h, h16* __restrict__ a1h)
{
    int blk = blockIdx.x;
    if (blk >= 4256) {
        int i = (blk - 4256) * 1024 + threadIdx.x * 4;
        float4 v = *reinterpret_cast<const float4*>(x + i);
        __half2* ph = reinterpret_cast<__half2*>(a1h + i);
        ph[0] = __half2(__float2half_rn(v.x), __float2half_rn(v.y));
        ph[1] = __half2(__float2half_rn(v.z), __float2half_rn(v.w));
        return;
    }

    __shared__ float t[32][33];
    const float* in;
    h16 *oh, *ol = nullptr;
    int R, C, bx, by;
    if (blk < 2048)      { in = W_in;   oh = b1h; R = 1024; C = 2048; bx = blk % 64; by = blk / 64; }
    else if (blk < 2144) { blk -= 2048; in = W_xdbl; oh = bxh; R = 1024; C = 96;   bx = blk % 3;  by = blk / 3; }
    else if (blk < 2208) { blk -= 2144; in = W_dt;  oh = bdh; ol = bdl; R = 64; C = 1024; bx = blk % 32; by = blk / 32; }
    else                 { blk -= 2208; in = W_out; oh = b2h; R = 2048; C = 1024; bx = blk % 32; by = blk / 32; }

    const int cx = bx * 32, ry = by * 32;
    const int tx = threadIdx.x & 31, ty = threadIdx.x >> 5;   // 32 x 8
    #pragma unroll
    for (int j = ty; j < 32; j += 8)
        t[j][tx] = in[(size_t)(ry + j) * C + cx + tx];
    __syncthreads();
    #pragma unroll
    for (int j = ty; j < 32; j += 8) {
        float v = t[tx][j];
        h16 h, l; split_h16(v, h, l);
        size_t o = (size_t)(cx + j) * R + ry + tx;
        oh[o] = h;
        if (ol) ol[o] = l;
    }
}

// ---------------------------------------------------------------------------
// Depthwise conv (k=4, SAME: pad left 1, right 2) + SiLU over BOTH halves,
// half2-vectorized: each thread handles 2 channels x 4 consecutive l outputs.
// ---------------------------------------------------------------------------
__global__ __launch_bounds__(256)
void conv_both_kernel(const h16* __restrict__ xz,
                      const float* __restrict__ wx, const float* __restrict__ bx,
                      const float* __restrict__ wz, const float* __restrict__ bz,
                      h16* __restrict__ xsh, h16* __restrict__ xsl,
                      h16* __restrict__ ch)
{
    const int half = blockIdx.y;
    const float* w    = half ? wz : wx;
    const float* bias = half ? bz : bx;
    const int col0 = half ? DHALF : 0;

    int idx = blockIdx.x * blockDim.x + threadIdx.x;   // < MROWS/4 * DHALF/2
    int c2  = (idx & 511) << 1;
    int bl4 = idx >> 9;
    int b   = bl4 >> 9;
    int l0  = (bl4 & 511) << 2;

    float2 w0 = *reinterpret_cast<const float2*>(w + c2);
    float2 w1 = *reinterpret_cast<const float2*>(w + DHALF + c2);
    float2 w2 = *reinterpret_cast<const float2*>(w + 2 * DHALF + c2);
    float2 w3 = *reinterpret_cast<const float2*>(w + 3 * DHALF + c2);
    float2 bv = *reinterpret_cast<const float2*>(bias + c2);

    const __half2* src = reinterpret_cast<const __half2*>(
        xz + (size_t)b * LSEQ * DINNER + col0 + c2);
    float2 win[7];
    #pragma unroll
    for (int j = 0; j < 7; j++) {
        int l = l0 + j - 1;
        win[j] = (l >= 0 && l < LSEQ)
                 ? __half22float2(src[(size_t)l * (DINNER / 2)])
                 : make_float2(0.0f, 0.0f);
    }

    #pragma unroll
    for (int k = 0; k < 4; k++) {
        float ax = bv.x, ay = bv.y;
        ax = fmaf(win[k].x,     w0.x, ax); ay = fmaf(win[k].y,     w0.y, ay);
        ax = fmaf(win[k + 1].x, w1.x, ax); ay = fmaf(win[k + 1].y, w1.y, ay);
        ax = fmaf(win[k + 2].x, w2.x, ax); ay = fmaf(win[k + 2].y, w2.y, ay);
        ax = fmaf(win[k + 3].x, w3.x, ax); ay = fmaf(win[k + 3].y, w3.y, ay);
        float vx = silu_f(ax), vy = silu_f(ay);
        size_t row = (size_t)b * LSEQ + l0 + k;
        if (half == 0) {
            h16 hx, lx, hy, ly;
            split_h16(vx, hx, lx); split_h16(vy, hy, ly);
            size_t o = row * DHALF + c2;
            *reinterpret_cast<__half2*>(xsh + o) = __half2(hx, hy);
            *reinterpret_cast<__half2*>(xsl + o) = __half2(lx, ly);
        } else {
            *reinterpret_cast<__half2*>(ch + row * DINNER + DHALF + c2) =
                __half2(__float2half_rn(vx), __float2half_rn(vy));
        }
    }
}

// ---------------------------------------------------------------------------
// Chunk-parallel selective scan.  A[d][n] = -(n+1) => dA_n = exp(-delta)^(n+1).
//   NCHUNK=32, LCHUNK=64 -> 1024 blocks in phases 1 and 3.
// u is read hi-only (fp16 rn).
// ---------------------------------------------------------------------------
#define PW16(p1, pw)                                                    \
    float p2 = (p1) * (p1), p3 = p2 * (p1), p4 = p2 * p2;               \
    float p5 = p4 * (p1), p6 = p4 * p2, p7 = p4 * p3, p8 = p4 * p4;     \
    float pw[16] = {(p1), p2, p3, p4, p5, p6, p7, p8,                   \
                    p8 * (p1), p8 * p2, p8 * p3, p8 * p4,               \
                    p8 * p5, p8 * p6, p8 * p7, p8 * p8};

__global__ __launch_bounds__(128)
void scan_p1(const float* __restrict__ delta,
             const h16* __restrict__ uh,
             const float* __restrict__ xdbl,
             float* __restrict__ q, float* __restrict__ S)
{
    const int tid = threadIdx.x;
    const int chunk = blockIdx.x, dblk = blockIdx.y, b = blockIdx.z;
    const int d = (dblk << 7) + tid;

    __shared__ float sB[16][DSTATE];
    __shared__ float sd[16][128];
    __shared__ float su[16][128];

    float h[DSTATE];
    #pragma unroll
    for (int n = 0; n < DSTATE; n++) h[n] = 0.0f;
    float sum = 0.0f;
    const size_t baseRow = (size_t)b * LSEQ + (size_t)chunk * LCHUNK;

    for (int t0 = 0; t0 < LCHUNK; t0 += 16) {
        {
            int s = tid >> 3;
            int i = (tid & 7) << 1;
            float2 v = *reinterpret_cast<const float2*>(
                xdbl + (baseRow + t0 + s) * XDBL_N + DTRANK + i);
            sB[s][i] = v.x; sB[s][i + 1] = v.y;
        }
        #pragma unroll
        for (int s = 0; s < 16; s++) {
            size_t r = (baseRow + t0 + s) * DHALF + d;
            sd[s][tid] = delta[r];
            su[s][tid] = __half2float(uh[r]);
        }
        __syncthreads();

        #pragma unroll
        for (int s = 0; s < 16; s++) {
            float dl = sd[s][tid];
            float du = dl * su[s][tid];
            sum += dl;
            float p1 = __expf(-dl);
            PW16(p1, pw)
            #pragma unroll
            for (int n = 0; n < DSTATE; n++)
                h[n] = fmaf(pw[n], h[n], du * sB[s][n]);
        }
        __syncthreads();
    }
    const size_t cbase = ((size_t)(b * NCHUNK + chunk) * DSTATE) * DHALF + d;
    #pragma unroll
    for (int n = 0; n < DSTATE; n++) q[cbase + (size_t)n * DHALF] = h[n];
    S[(size_t)(b * NCHUNK + chunk) * DHALF + d] = sum;
}

__global__ __launch_bounds__(128)
void scan_p2(const float* __restrict__ q, const float* __restrict__ S,
             float* __restrict__ hs)
{
    const int idx = blockIdx.x * 128 + threadIdx.x;   // < 4096
    const int b = idx >> 10, d = idx & (DHALF - 1);
    float h[DSTATE];
    #pragma unroll
    for (int n = 0; n < DSTATE; n++) h[n] = 0.0f;
    for (int c = 0; c < NCHUNK; c++) {
        const size_t cbase = ((size_t)(b * NCHUNK + c) * DSTATE) * DHALF + d;
        #pragma unroll
        for (int n = 0; n < DSTATE; n++) hs[cbase + (size_t)n * DHALF] = h[n];
        float s = S[(size_t)(b * NCHUNK + c) * DHALF + d];
        float p1 = __expf(-s);
        PW16(p1, pw)
        #pragma unroll
        for (int n = 0; n < DSTATE; n++)
            h[n] = fmaf(pw[n], h[n], q[cbase + (size_t)n * DHALF]);
    }
}

__global__ __launch_bounds__(128)
void scan_p3(const float* __restrict__ delta,
             const h16* __restrict__ uh,
             const float* __restrict__ xdbl, const float* __restrict__ hs,
             const float* __restrict__ Dv,
             h16* __restrict__ cat_h)
{
    const int tid = threadIdx.x;
    const int chunk = blockIdx.x, dblk = blockIdx.y, b = blockIdx.z;
    const int d = (dblk << 7) + tid;

    __shared__ float sB[16][DSTATE];
    __shared__ float sC[16][DSTATE];
    __shared__ float sd[16][128];
    __shared__ float su[16][128];

    float h[DSTATE];
    const size_t cbase = ((size_t)(b * NCHUNK + chunk) * DSTATE) * DHALF + d;
    #pragma unroll
    for (int n = 0; n < DSTATE; n++) h[n] = hs[cbase + (size_t)n * DHALF];
    const float Dd = Dv[d];
    const size_t baseRow = (size_t)b * LSEQ + (size_t)chunk * LCHUNK;

    for (int t0 = 0; t0 < LCHUNK; t0 += 16) {
        {
            int s = tid >> 3;
            int i = (tid & 7) << 2;
            float4 v = *reinterpret_cast<const float4*>(
                xdbl + (baseRow + t0 + s) * XDBL_N + DTRANK + i);
            float vv[4] = {v.x, v.y, v.z, v.w};
            #pragma unroll
            for (int qq = 0; qq < 4; qq++) {
                int ii = i + qq;
                if (ii < DSTATE) sB[s][ii] = vv[qq];
                else             sC[s][ii - DSTATE] = vv[qq];
            }
        }
        #pragma unroll
        for (int s = 0; s < 16; s++) {
            size_t r = (baseRow + t0 + s) * DHALF + d;
            sd[s][tid] = delta[r];
            su[s][tid] = __half2float(uh[r]);
        }
        __syncthreads();

        #pragma unroll
        for (int s = 0; s < 16; s++) {
            float dl = sd[s][tid];
            float uu = su[s][tid];
            float du = dl * uu;
            float p1 = __expf(-dl);
            PW16(p1, pw)
            float y0 = 0.f, y1 = 0.f, y2 = 0.f, y3 = 0.f;
            #pragma unroll
            for (int n = 0; n < DSTATE; n += 4) {
                h[n + 0] = fmaf(pw[n + 0], h[n + 0], du * sB[s][n + 0]);
                h[n + 1] = fmaf(pw[n + 1], h[n + 1], du * sB[s][n + 1]);
                h[n + 2] = fmaf(pw[n + 2], h[n + 2], du * sB[s][n + 2]);
                h[n + 3] = fmaf(pw[n + 3], h[n + 3], du * sB[s][n + 3]);
                y0 = fmaf(h[n + 0], sC[s][n + 0], y0);
                y1 = fmaf(h[n + 1], sC[s][n + 1], y1);
                y2 = fmaf(h[n + 2], sC[s][n + 2], y2);
                y3 = fmaf(h[n + 3], sC[s][n + 3], y3);
            }
            float yv = fmaf(uu, Dd, (y0 + y1) + (y2 + y3));
            cat_h[(baseRow + t0 + s) * DINNER + d] = __float2half_rn(yv);
        }
        __syncthreads();
    }
}

// ---------------------------------------------------------------------------
// Launch
// ---------------------------------------------------------------------------
extern "C" void kernel_launch(void* const* d_in, const int* in_sizes, int n_in,
                              void* d_out, int out_size)
{
    const float* x        = (const float*)d_in[0];
    const float* W_in     = (const float*)d_in[1];
    const float* conv_x_w = (const float*)d_in[2];
    const float* conv_x_b = (const float*)d_in[3];
    const float* conv_z_w = (const float*)d_in[4];
    const float* conv_z_b = (const float*)d_in[5];
    const float* W_xdbl   = (const float*)d_in[6];
    const float* W_dt     = (const float*)d_in[7];
    const float* inv_dt   = (const float*)d_in[8];
    const float* Dvec     = (const float*)d_in[9];
    const float* W_out    = (const float*)d_in[10];
    const float* b_out    = (const float*)d_in[11];
    float* out            = (float*)d_out;

    float *p_xdbl, *p_xp, *p_delta, *p_q, *p_hs, *p_S;
    h16 *p_xzh, *p_a1h, *p_b1h, *p_xsh, *p_xsl, *p_bxh;
    h16 *p_dth, *p_dtl, *p_bdh, *p_bdl, *p_ch, *p_b2h;
    cudaGetSymbolAddress((void**)&p_xzh,   g_xzh);
    cudaGetSymbolAddress((void**)&p_xdbl,  g_xdbl);
    cudaGetSymbolAddress((void**)&p_xp,    g_xp);
    cudaGetSymbolAddress((void**)&p_delta, g_delta);
    cudaGetSymbolAddress((void**)&p_q,  g_q);
    cudaGetSymbolAddress((void**)&p_hs, g_hs);
    cudaGetSymbolAddress((void**)&p_S,  g_S);
    cudaGetSymbolAddress((void**)&p_a1h, g_a1h);
    cudaGetSymbolAddress((void**)&p_b1h, g_b1h);
    cudaGetSymbolAddress((void**)&p_xsh, g_xsh); cudaGetSymbolAddress((void**)&p_xsl, g_xsl);
    cudaGetSymbolAddress((void**)&p_bxh, g_bxh);
    cudaGetSymbolAddress((void**)&p_dth, g_dth); cudaGetSymbolAddress((void**)&p_dtl, g_dtl);
    cudaGetSymbolAddress((void**)&p_bdh, g_bdh); cudaGetSymbolAddress((void**)&p_bdl, g_bdl);
    cudaGetSymbolAddress((void**)&p_ch,  g_ch);
    cudaGetSymbolAddress((void**)&p_b2h, g_b2h);

    constexpr int SMEM_128 = 3 * (128 * 128 + 128 * 128) + 1024;   // 99328
    constexpr int SMEM_64  = 3 * (64 * 128 + 128 * 128) + 1024;    // 74752
    cudaFuncSetAttribute((const void*)gemm_mma<128,1,false,false,false,false,true>,
                         cudaFuncAttributeMaxDynamicSharedMemorySize, SMEM_128);
    cudaFuncSetAttribute((const void*)gemm_mma<128,1,false,true,false,false,false>,
                         cudaFuncAttributeMaxDynamicSharedMemorySize, SMEM_128);
    cudaFuncSetAttribute((const void*)gemm_mma<128,3,true,true,false,false,false>,
                         cudaFuncAttributeMaxDynamicSharedMemorySize, SMEM_128);
    cudaFuncSetAttribute((const void*)gemm_mma<64,2,false,false,true,false,false>,
                         cudaFuncAttributeMaxDynamicSharedMemorySize, SMEM_64);

    // 1) all prep in ONE launch: 4 weight transposes/splits + x->fp16
    prep_kernel<<<4256 + 8192, 256>>>(W_in, W_xdbl, W_dt, W_out, x,
                                      p_b1h, p_bxh, p_bdh, p_bdl, p_b2h, p_a1h);

    // 2) xz = x @ W_in                              [8192,2048]  (1-stream, fp16 out)
    gemm_mma<128,1,false,false,false,false,true><<<dim3(DINNER / 128, MROWS / 128), 256, SMEM_128>>>(
        p_a1h, nullptr, p_b1h, nullptr, nullptr, 0.0f, p_xzh, DINNER, DMODEL, DMODEL,
        DINNER, nullptr, nullptr);

    // 3) both depthwise convs + silu (half2-vectorized, one launch)
    conv_both_kernel<<<dim3((MROWS / 4 * DHALF / 2) / 256, 2), 256>>>(
        p_xzh, conv_x_w, conv_x_b, conv_z_w, conv_z_b, p_xsh, p_xsl, p_ch);

    // 4) x_dbl = xs @ W_xdbl  [8192,96] (2-stream, split-K=4 -> 512 CTAs)
    gemm_mma<64,2,false,false,true,false,false>
        <<<dim3(1, MROWS / 64, KSPLIT), 256, SMEM_64>>>(
        p_xsh, p_xsl, p_bxh, nullptr, nullptr, 0.0f, p_xp, XDBL_N,
        DHALF / KSPLIT, DHALF, XDBL_N, nullptr, nullptr);

    // 4b) reduce partials -> xdbl (fp32) + dt hi/lo split
    reduce_xdbl_kernel<<<(MROWS * XDBL_N / 4) / 256, 256>>>(p_xp, p_xdbl, p_dth, p_dtl);

    // 5) delta = softplus(dt_low @ W_dt + 2*inv_dt) [8192,1024] (3-stream)
    gemm_mma<128,3,true,true,false,false,false><<<dim3(DHALF / 128, MROWS / 128), 256, SMEM_128>>>(
        p_dth, p_dtl, p_bdh, p_bdl, inv_dt, 2.0f, p_delta, DHALF, DTRANK, DTRANK,
        DHALF, nullptr, nullptr);

    // 6) chunk-parallel selective scan (32 chunks) -> concat left half (fp16 rn)
    scan_p1<<<dim3(NCHUNK, 8, B_SZ), 128>>>(p_delta, p_xsh, p_xdbl, p_q, p_S);
    scan_p2<<<32, 128>>>(p_q, p_S, p_hs);
    scan_p3<<<dim3(NCHUNK, 8, B_SZ), 128>>>(p_delta, p_xsh, p_xdbl, p_hs, Dvec, p_ch);

    // 7) out = [y|z] @ W_out + b_out                [8192,1024]  (1-stream)
    gemm_mma<128,1,false,true,false,false,false><<<dim3(DMODEL / 128, MROWS / 128), 256, SMEM_128>>>(
        p_ch, nullptr, p_b2h, nullptr, b_out, 1.0f, out, DMODEL, DINNER, DINNER,
        DMODEL, nullptr, nullptr);
}

// round 15
// speedup vs baseline: 1.0177x; 1.0177x over previous
#include <cuda_runtime.h>
#include <cuda_fp16.h>
#include <cstdint>
#include <cstddef>

// ---------------------------------------------------------------------------
// Problem constants (MambaVisionMixer, B=4, L=2048)
// ---------------------------------------------------------------------------
#define B_SZ    4
#define LSEQ    2048
#define DMODEL  1024
#define DINNER  2048
#define DHALF   1024
#define DSTATE  16
#define DTRANK  64
#define XDBL_N  96
#define MROWS   (B_SZ*LSEQ)   // 8192
#define NCHUNK  32
#define LCHUNK  (LSEQ/NCHUNK) // 64

typedef __half h16;

// ---------------------------------------------------------------------------
// Device scratch (static __device__ arrays — no allocations)
// ---------------------------------------------------------------------------
__device__ h16   g_xzh [(size_t)MROWS * DINNER];    // xz fp16  (32 MB)
__device__ float g_xdbl [(size_t)MROWS * XDBL_N];   // 3 MB
__device__ float g_delta[(size_t)MROWS * DHALF];    // 32 MB

__device__ float g_q [(size_t)B_SZ * NCHUNK * DSTATE * DHALF];  // 8 MB
__device__ float g_hs[(size_t)B_SZ * NCHUNK * DSTATE * DHALF];  // 8 MB
__device__ float g_S [(size_t)B_SZ * NCHUNK * DHALF];           // 512 KB

__device__ h16 g_a1h[(size_t)MROWS * DMODEL];      // x (fp16 rn)
__device__ h16 g_b1h[(size_t)DINNER * DMODEL];     // W_in^T  [2048,1024]
__device__ h16 g_xsh[(size_t)MROWS * DHALF];       // xs hi
__device__ h16 g_xsl[(size_t)MROWS * DHALF];       // xs lo (xdbl path only)
__device__ h16 g_bxh[(size_t)XDBL_N * DHALF];      // W_xdbl^T [96,1024]
__device__ h16 g_dth[(size_t)MROWS * DTRANK];      // dt_low hi [8192,64]
__device__ h16 g_dtl[(size_t)MROWS * DTRANK];
__device__ h16 g_bdh[(size_t)DHALF * DTRANK];      // W_dt^T [1024,64]
__device__ h16 g_ch [(size_t)MROWS * DINNER];      // [y|z] (fp16 rn) [8192,2048]
__device__ h16 g_b2h[(size_t)DMODEL * DINNER];     // W_out^T [1024,2048]

// ---------------------------------------------------------------------------
// Helpers (sm_80-era ISA only: compiles at compute_103 non-'a' target)
// ---------------------------------------------------------------------------
__device__ __forceinline__ uint32_t smem_u32(const void* p) {
    uint32_t r;
    asm("{ .reg .u64 t; cvta.to.shared.u64 t, %1; cvt.u32.u64 %0, t; }"
        : "=r"(r) : "l"(p));
    return r;
}

#define CP16(dst, src) \
    asm volatile("cp.async.cg.shared.global [%0], [%1], 16;" \
        :: "r"(dst), "l"(src) : "memory")
#define CP16Z(dst, src, sz) \
    asm volatile("cp.async.cg.shared.global [%0], [%1], 16, %2;" \
        :: "r"(dst), "l"(src), "r"(sz) : "memory")
#define CP_COMMIT() asm volatile("cp.async.commit_group;" ::: "memory")
#define CP_WAIT2()  asm volatile("cp.async.wait_group 2;" ::: "memory")

__device__ __forceinline__ void ldsm4(uint32_t* r, uint32_t addr) {
    asm volatile("ldmatrix.sync.aligned.m8n8.x4.shared.b16 {%0,%1,%2,%3}, [%4];"
        : "=r"(r[0]), "=r"(r[1]), "=r"(r[2]), "=r"(r[3]) : "r"(addr));
}

__device__ __forceinline__ void mma16816(float* d, const uint32_t* a,
                                         const uint32_t* b) {
    asm volatile(
        "mma.sync.aligned.m16n8k16.row.col.f32.f16.f16.f32 "
        "{%0,%1,%2,%3}, {%4,%5,%6,%7}, {%8,%9}, {%0,%1,%2,%3};"
        : "+f"(d[0]), "+f"(d[1]), "+f"(d[2]), "+f"(d[3])
        : "r"(a[0]), "r"(a[1]), "r"(a[2]), "r"(a[3]), "r"(b[0]), "r"(b[1]));
}

__device__ __forceinline__ float softplus_f(float x) {
    return fmaxf(x, 0.0f) + log1pf(expf(-fabsf(x)));
}
__device__ __forceinline__ float silu_f(float x) {
    return x / (1.0f + expf(-x));
}
__device__ __forceinline__ void split_h16(float v, h16& h, h16& l) {
    h = __float2half_rn(v);
    l = __float2half_rn(v - __half2float(h));
}

// ---------------------------------------------------------------------------
// Tensor-core GEMM (mma.sync fp16, fp32 accum), extended-K streams.
//   C[M,N] = A[M,K] @ B^T   (B stored [N,K] row-major)
//   NSTREAM==1: (Ahi,Bhi)
//   NSTREAM==2: (Ahi,Bhi), (Alo,Bhi)
//   NSTREAM==3: (Ahi,Bhi), (Ahi,Blo), (Alo,Bhi)
//   CTA BMx128, 8 warps (2x4), warp tile (BM/2)x32, BK=64,
//   3-stage cp.async pipeline.  H16OUT: write C as fp16 rn.
//   DTSPLIT: additionally write fp16 hi/lo of cols [0,64) to dth/dtl.
// ---------------------------------------------------------------------------
template <int BM, int NSTREAM, bool SOFTPLUS, bool HASBIAS, bool NCHK,
          bool DTSPLIT, bool H16OUT>
__global__ __launch_bounds__(256, 2)
void gemm_mma(const h16* __restrict__ Ahi, const h16* __restrict__ Alo,
              const h16* __restrict__ Bhi, const h16* __restrict__ Blo,
              const float* __restrict__ bias, float bias_scale,
              void* __restrict__ Cout, int N, int K, int Brows,
              h16* __restrict__ dth, h16* __restrict__ dtl)
{
    constexpr int MI     = BM / 32;
    constexpr int ABYTES = BM * 128;
    constexpr int STAGE  = ABYTES + 128 * 128;
    extern __shared__ char dsm[];
    const uint32_t base = (smem_u32(dsm) + 1023u) & ~1023u;

    const int tid    = threadIdx.x;
    const int rowBlk = blockIdx.y * BM;
    const int colBlk = blockIdx.x * 128;
    const int wid    = tid >> 5;
    const int lane   = tid & 31;
    const int warp_m = wid >> 2;
    const int warp_n = wid & 3;
    const int mat    = lane >> 3;
    const int rin    = lane & 7;

    const int KC     = K / 64;
    const int CHUNKS = NSTREAM * KC;

    uint32_t offA[MI][4], offB[2][4];
    #pragma unroll
    for (int mi = 0; mi < MI; mi++)
        #pragma unroll
        for (int j = 0; j < 4; j++) {
            int row = warp_m * (BM / 2) + mi * 16 + (mat & 1) * 8 + rin;
            int c   = 2 * j + (mat >> 1);
            offA[mi][j] = row * 128 + ((c ^ (row & 7)) << 4);
        }
    #pragma unroll
    for (int bi = 0; bi < 2; bi++)
        #pragma unroll
        for (int j = 0; j < 4; j++) {
            int row = warp_n * 32 + bi * 16 + (mat >> 1) * 8 + rin;
            int c   = 2 * j + (mat & 1);
            offB[bi][j] = ABYTES + row * 128 + ((c ^ (row & 7)) << 4);
        }

    float acc[MI][4][4];
    #pragma unroll
    for (int i = 0; i < MI; i++)
        #pragma unroll
        for (int j = 0; j < 4; j++)
            #pragma unroll
            for (int q = 0; q < 4; q++) acc[i][j][q] = 0.0f;

    auto load_stage = [&](int s, int c) {
        int stream;
        if (NSTREAM == 1)      stream = 0;
        else if (NSTREAM == 2) stream = (c >= KC) ? 1 : 0;
        else                   stream = (c >= 2 * KC) ? 2 : ((c >= KC) ? 1 : 0);
        int k0 = (c - stream * KC) * 64;
        const h16* Ap = Ahi;
        const h16* Bp = Bhi;
        if (NSTREAM == 2) {
            if (stream == 1) Ap = Alo;
        } else if (NSTREAM == 3) {
            if (stream == 2) Ap = Alo;
            else if (stream == 1) Bp = Blo;
        }
        uint32_t as_ = base + s * STAGE;
        uint32_t bs_ = as_ + ABYTES;
        #pragma unroll
        for (int t = 0; t < BM / 32; t++) {
            int idx = tid + t * 256;
            int r = idx >> 3, cc = idx & 7;
            uint32_t dst = as_ + r * 128 + ((cc ^ (r & 7)) << 4);
            const char* src =
                (const char*)(Ap + (size_t)(rowBlk + r) * K + k0) + cc * 16;
            CP16(dst, src);
        }
        #pragma unroll
        for (int t = 0; t < 4; t++) {
            int idx = tid + t * 256;
            int r = idx >> 3, cc = idx & 7;
            uint32_t dst = bs_ + r * 128 + ((cc ^ (r & 7)) << 4);
            if (NCHK) {
                int br = colBlk + r;
                int ok = (br < Brows);
                const char* src =
                    (const char*)(Bp + (size_t)(ok ? br : 0) * K + k0) + cc * 16;
                CP16Z(dst, src, ok ? 16u : 0u);
            } else {
                const char* src =
                    (const char*)(Bp + (size_t)(colBlk + r) * K + k0) + cc * 16;
                CP16(dst, src);
            }
        }
    };

    #pragma unroll
    for (int s = 0; s < 3; s++) { load_stage(s, s); CP_COMMIT(); }

    int slot = 0;
    #pragma unroll 1
    for (int i = 0; i < CHUNKS; i++) {
        CP_WAIT2();
        __syncthreads();
        const uint32_t sb = base + slot * STAGE;
        #pragma unroll
        for (int j = 0; j < 4; j++) {
            uint32_t Af[MI][4];
            #pragma unroll
            for (int mi = 0; mi < MI; mi++) ldsm4(Af[mi], sb + offA[mi][j]);
            uint32_t Bf[4][2];
            #pragma unroll
            for (int bi = 0; bi < 2; bi++) {
                uint32_t r[4];
                ldsm4(r, sb + offB[bi][j]);
                Bf[bi * 2 + 0][0] = r[0]; Bf[bi * 2 + 0][1] = r[1];
                Bf[bi * 2 + 1][0] = r[2]; Bf[bi * 2 + 1][1] = r[3];
            }
            #pragma unroll
            for (int mi = 0; mi < MI; mi++)
                #pragma unroll
                for (int ni = 0; ni < 4; ni++)
                    mma16816(acc[mi][ni], Af[mi], Bf[ni]);
        }
        __syncthreads();
        if (i + 3 < CHUNKS) load_stage(slot, i + 3);
        CP_COMMIT();
        slot = (slot == 2) ? 0 : slot + 1;
    }

    // epilogue
    const int mrow = rowBlk + warp_m * (BM / 2) + (lane >> 2);
    const int ncol = colBlk + warp_n * 32 + (lane & 3) * 2;
    #pragma unroll
    for (int mi = 0; mi < MI; mi++) {
        #pragma unroll
        for (int ni = 0; ni < 4; ni++) {
            int n0 = ncol + ni * 8;
            if (NCHK && n0 >= Brows) continue;
            float v0 = acc[mi][ni][0], v1 = acc[mi][ni][1];
            float v2 = acc[mi][ni][2], v3 = acc[mi][ni][3];
            if (HASBIAS) {
                float b0 = bias_scale * __ldg(bias + n0);
                float b1 = bias_scale * __ldg(bias + n0 + 1);
                v0 += b0; v1 += b1; v2 += b0; v3 += b1;
            }
            if (SOFTPLUS) {
                v0 = softplus_f(v0); v1 = softplus_f(v1);
                v2 = softplus_f(v2); v3 = softplus_f(v3);
            }
            size_t r0 = (size_t)(mrow + mi * 16) * N + n0;
            size_t r1 = (size_t)(mrow + mi * 16 + 8) * N + n0;
            if (H16OUT) {
                h16* Ch = reinterpret_cast<h16*>(Cout);
                *reinterpret_cast<__half2*>(Ch + r0) =
                    __half2(__float2half_rn(v0), __float2half_rn(v1));
                *reinterpret_cast<__half2*>(Ch + r1) =
                    __half2(__float2half_rn(v2), __float2half_rn(v3));
            } else {
                float* Cf = reinterpret_cast<float*>(Cout);
                *reinterpret_cast<float2*>(Cf + r0) = make_float2(v0, v1);
                *reinterpret_cast<float2*>(Cf + r1) = make_float2(v2, v3);
            }
            if (DTSPLIT && n0 < DTRANK) {
                h16 hh, ll;
                size_t d0 = (size_t)(mrow + mi * 16) * DTRANK + n0;
                size_t d1 = (size_t)(mrow + mi * 16 + 8) * DTRANK + n0;
                split_h16(v0, hh, ll); dth[d0] = hh;     dtl[d0] = ll;
                split_h16(v1, hh, ll); dth[d0 + 1] = hh; dtl[d0 + 1] = ll;
                split_h16(v2, hh, ll); dth[d1] = hh;     dtl[d1] = ll;
                split_h16(v3, hh, ll); dth[d1 + 1] = hh; dtl[d1 + 1] = ll;
            }
        }
    }
}

// ---------------------------------------------------------------------------
// Combined prep — ONE launch: 4 weight transposes AND x -> fp16.
//   blk ranges:
//     [0,    2048): W_in  [1024,2048] -> b1h [2048,1024]          (hi only)
//     [2048, 2144): W_xdbl[1024,  96] -> bxh [  96,1024]          (hi only)
//     [2144, 2208): W_dt  [  64,1024] -> bdh [1024,64]            (hi only)
//     [2208, 4256): W_out [2048,1024] -> b2h [1024,2048]          (hi only)
//     [4256,12448): x (8M floats) -> a1h fp16 rn (1024 elems/blk)
// ---------------------------------------------------------------------------
__global__ __launch_bounds__(256)
void prep_kernel(const float* __restrict__ W_in,
                 const float* __restrict__ W_xdbl,
                 const float* __restrict__ W_dt,
                 const float* __restrict__ W_out,
                 const float* __restrict__ x,
                 h16* __restrict__ b1h, h16* __restrict__ bxh,
                 h16* __restrict__ bdh,
                 h16* __restrict__ b2h, h16* __restrict__ a1h)
{
    int blk = blockIdx.x;
    if (blk >= 4256) {
        int i = (blk - 4256) * 1024 + threadIdx.x * 4;
        float4 v = *reinterpret_cast<const float4*>(x + i);
        __half2* ph = reinterpret_cast<__half2*>(a1h + i);
        ph[0] = __half2(__float2half_rn(v.x), __float2half_rn(v.y));
        ph[1] = __half2(__float2half_rn(v.z), __float2half_rn(v.w));
        return;
    }

    __shared__ float t[32][33];
    const float* in;
    h16 *oh;
    int R, C, bx, by;
    if (blk < 2048)      { in = W_in;   oh = b1h; R = 1024; C = 2048; bx = blk % 64; by = blk / 64; }
    else if (blk < 2144) { blk -= 2048; in = W_xdbl; oh = bxh; R = 1024; C = 96;   bx = blk % 3;  by = blk / 3; }
    else if (blk < 2208) { blk -= 2144; in = W_dt;  oh = bdh; R = 64; C = 1024; bx = blk % 32; by = blk / 32; }
    else                 { blk -= 2208; in = W_out; oh = b2h; R = 2048; C = 1024; bx = blk % 32; by = blk / 32; }

    const int cx = bx * 32, ry = by * 32;
    const int tx = threadIdx.x & 31, ty = threadIdx.x >> 5;   // 32 x 8
    #pragma unroll
    for (int j = ty; j < 32; j += 8)
        t[j][tx] = in[(size_t)(ry + j) * C + cx + tx];
    __syncthreads();
    #pragma unroll
    for (int j = ty; j < 32; j += 8) {
        float v = t[tx][j];
        size_t o = (size_t)(cx + j) * R + ry + tx;
        oh[o] = __float2half_rn(v);
    }
}

// ---------------------------------------------------------------------------
// Depthwise conv (k=4, SAME: pad left 1, right 2) + SiLU over BOTH halves,
// half2-vectorized: each thread handles 2 channels x 4 consecutive l outputs.
//   blockIdx.y == 0: x-half -> split fp16 (xsh + xsl)
//   blockIdx.y == 1: z-half -> fp16 rn into concat right half (stride DINNER)
// ---------------------------------------------------------------------------
__global__ __launch_bounds__(256)
void conv_both_kernel(const h16* __restrict__ xz,
                      const float* __restrict__ wx, const float* __restrict__ bx,
                      const float* __restrict__ wz, const float* __restrict__ bz,
                      h16* __restrict__ xsh, h16* __restrict__ xsl,
                      h16* __restrict__ ch)
{
    const int half = blockIdx.y;
    const float* w    = half ? wz : wx;
    const float* bias = half ? bz : bx;
    const int col0 = half ? DHALF : 0;

    int idx = blockIdx.x * blockDim.x + threadIdx.x;   // < MROWS/4 * DHALF/2
    int c2  = (idx & 511) << 1;
    int bl4 = idx >> 9;
    int b   = bl4 >> 9;
    int l0  = (bl4 & 511) << 2;

    float2 w0 = *reinterpret_cast<const float2*>(w + c2);
    float2 w1 = *reinterpret_cast<const float2*>(w + DHALF + c2);
    float2 w2 = *reinterpret_cast<const float2*>(w + 2 * DHALF + c2);
    float2 w3 = *reinterpret_cast<const float2*>(w + 3 * DHALF + c2);
    float2 bv = *reinterpret_cast<const float2*>(bias + c2);

    const __half2* src = reinterpret_cast<const __half2*>(
        xz + (size_t)b * LSEQ * DINNER + col0 + c2);
    float2 win[7];
    #pragma unroll
    for (int j = 0; j < 7; j++) {
        int l = l0 + j - 1;
        win[j] = (l >= 0 && l < LSEQ)
                 ? __half22float2(src[(size_t)l * (DINNER / 2)])
                 : make_float2(0.0f, 0.0f);
    }

    #pragma unroll
    for (int k = 0; k < 4; k++) {
        float ax = bv.x, ay = bv.y;
        ax = fmaf(win[k].x,     w0.x, ax); ay = fmaf(win[k].y,     w0.y, ay);
        ax = fmaf(win[k + 1].x, w1.x, ax); ay = fmaf(win[k + 1].y, w1.y, ay);
        ax = fmaf(win[k + 2].x, w2.x, ax); ay = fmaf(win[k + 2].y, w2.y, ay);
        ax = fmaf(win[k + 3].x, w3.x, ax); ay = fmaf(win[k + 3].y, w3.y, ay);
        float vx = silu_f(ax), vy = silu_f(ay);
        size_t row = (size_t)b * LSEQ + l0 + k;
        if (half == 0) {
            h16 hx, lx, hy, ly;
            split_h16(vx, hx, lx); split_h16(vy, hy, ly);
            size_t o = row * DHALF + c2;
            *reinterpret_cast<__half2*>(xsh + o) = __half2(hx, hy);
            *reinterpret_cast<__half2*>(xsl + o) = __half2(lx, ly);
        } else {
            *reinterpret_cast<__half2*>(ch + row * DINNER + DHALF + c2) =
                __half2(__float2half_rn(vx), __float2half_rn(vy));
        }
    }
}

// ---------------------------------------------------------------------------
// Chunk-parallel selective scan.  A[d][n] = -(n+1) => dA_n = exp(-delta)^(n+1).
//   NCHUNK=32, LCHUNK=64 -> 1024 blocks in phases 1 and 3.
// u is read hi-only (fp16 rn).
// ---------------------------------------------------------------------------
#define PW16(p1, pw)                                                    \
    float p2 = (p1) * (p1), p3 = p2 * (p1), p4 = p2 * p2;               \
    float p5 = p4 * (p1), p6 = p4 * p2, p7 = p4 * p3, p8 = p4 * p4;     \
    float pw[16] = {(p1), p2, p3, p4, p5, p6, p7, p8,                   \
                    p8 * (p1), p8 * p2, p8 * p3, p8 * p4,               \
                    p8 * p5, p8 * p6, p8 * p7, p8 * p8};

__global__ __launch_bounds__(128)
void scan_p1(const float* __restrict__ delta,
             const h16* __restrict__ uh,
             const float* __restrict__ xdbl,
             float* __restrict__ q, float* __restrict__ S)
{
    const int tid = threadIdx.x;
    const int chunk = blockIdx.x, dblk = blockIdx.y, b = blockIdx.z;
    const int d = (dblk << 7) + tid;

    __shared__ float sB[16][DSTATE];
    __shared__ float sd[16][128];
    __shared__ float su[16][128];

    float h[DSTATE];
    #pragma unroll
    for (int n = 0; n < DSTATE; n++) h[n] = 0.0f;
    float sum = 0.0f;
    const size_t baseRow = (size_t)b * LSEQ + (size_t)chunk * LCHUNK;

    for (int t0 = 0; t0 < LCHUNK; t0 += 16) {
        {
            int s = tid >> 3;
            int i = (tid & 7) << 1;
            float2 v = *reinterpret_cast<const float2*>(
                xdbl + (baseRow + t0 + s) * XDBL_N + DTRANK + i);
            sB[s][i] = v.x; sB[s][i + 1] = v.y;
        }
        #pragma unroll
        for (int s = 0; s < 16; s++) {
            size_t r = (baseRow + t0 + s) * DHALF + d;
            sd[s][tid] = delta[r];
            su[s][tid] = __half2float(uh[r]);
        }
        __syncthreads();

        #pragma unroll
        for (int s = 0; s < 16; s++) {
            float dl = sd[s][tid];
            float du = dl * su[s][tid];
            sum += dl;
            float p1 = __expf(-dl);
            PW16(p1, pw)
            #pragma unroll
            for (int n = 0; n < DSTATE; n++)
                h[n] = fmaf(pw[n], h[n], du * sB[s][n]);
        }
        __syncthreads();
    }
    const size_t cbase = ((size_t)(b * NCHUNK + chunk) * DSTATE) * DHALF + d;
    #pragma unroll
    for (int n = 0; n < DSTATE; n++) q[cbase + (size_t)n * DHALF] = h[n];
    S[(size_t)(b * NCHUNK + chunk) * DHALF + d] = sum;
}

__global__ __launch_bounds__(128)
void scan_p2(const float* __restrict__ q, const float* __restrict__ S,
             float* __restrict__ hs)
{
    const int idx = blockIdx.x * 128 + threadIdx.x;   // < 4096
    const int b = idx >> 10, d = idx & (DHALF - 1);
    float h[DSTATE];
    #pragma unroll
    for (int n = 0; n < DSTATE; n++) h[n] = 0.0f;
    for (int c = 0; c < NCHUNK; c++) {
        const size_t cbase = ((size_t)(b * NCHUNK + c) * DSTATE) * DHALF + d;
        #pragma unroll
        for (int n = 0; n < DSTATE; n++) hs[cbase + (size_t)n * DHALF] = h[n];
        float s = S[(size_t)(b * NCHUNK + c) * DHALF + d];
        float p1 = __expf(-s);
        PW16(p1, pw)
        #pragma unroll
        for (int n = 0; n < DSTATE; n++)
            h[n] = fmaf(pw[n], h[n], q[cbase + (size_t)n * DHALF]);
    }
}

__global__ __launch_bounds__(128)
void scan_p3(const float* __restrict__ delta,
             const h16* __restrict__ uh,
             const float* __restrict__ xdbl, const float* __restrict__ hs,
             const float* __restrict__ Dv,
             h16* __restrict__ cat_h)
{
    const int tid = threadIdx.x;
    const int chunk = blockIdx.x, dblk = blockIdx.y, b = blockIdx.z;
    const int d = (dblk << 7) + tid;

    __shared__ float sB[16][DSTATE];
    __shared__ float sC[16][DSTATE];
    __shared__ float sd[16][128];
    __shared__ float su[16][128];

    float h[DSTATE];
    const size_t cbase = ((size_t)(b * NCHUNK + chunk) * DSTATE) * DHALF + d;
    #pragma unroll
    for (int n = 0; n < DSTATE; n++) h[n] = hs[cbase + (size_t)n * DHALF];
    const float Dd = Dv[d];
    const size_t baseRow = (size_t)b * LSEQ + (size_t)chunk * LCHUNK;

    for (int t0 = 0; t0 < LCHUNK; t0 += 16) {
        {
            int s = tid >> 3;
            int i = (tid & 7) << 2;
            float4 v = *reinterpret_cast<const float4*>(
                xdbl + (baseRow + t0 + s) * XDBL_N + DTRANK + i);
            float vv[4] = {v.x, v.y, v.z, v.w};
            #pragma unroll
            for (int qq = 0; qq < 4; qq++) {
                int ii = i + qq;
                if (ii < DSTATE) sB[s][ii] = vv[qq];
                else             sC[s][ii - DSTATE] = vv[qq];
            }
        }
        #pragma unroll
        for (int s = 0; s < 16; s++) {
            size_t r = (baseRow + t0 + s) * DHALF + d;
            sd[s][tid] = delta[r];
            su[s][tid] = __half2float(uh[r]);
        }
        __syncthreads();

        #pragma unroll
        for (int s = 0; s < 16; s++) {
            float dl = sd[s][tid];
            float uu = su[s][tid];
            float du = dl * uu;
            float p1 = __expf(-dl);
            PW16(p1, pw)
            float y0 = 0.f, y1 = 0.f, y2 = 0.f, y3 = 0.f;
            #pragma unroll
            for (int n = 0; n < DSTATE; n += 4) {
                h[n + 0] = fmaf(pw[n + 0], h[n + 0], du * sB[s][n + 0]);
                h[n + 1] = fmaf(pw[n + 1], h[n + 1], du * sB[s][n + 1]);
                h[n + 2] = fmaf(pw[n + 2], h[n + 2], du * sB[s][n + 2]);
                h[n + 3] = fmaf(pw[n + 3], h[n + 3], du * sB[s][n + 3]);
                y0 = fmaf(h[n + 0], sC[s][n + 0], y0);
                y1 = fmaf(h[n + 1], sC[s][n + 1], y1);
                y2 = fmaf(h[n + 2], sC[s][n + 2], y2);
                y3 = fmaf(h[n + 3], sC[s][n + 3], y3);
            }
            float yv = fmaf(uu, Dd, (y0 + y1) + (y2 + y3));
            cat_h[(baseRow + t0 + s) * DINNER + d] = __float2half_rn(yv);
        }
        __syncthreads();
    }
}

// ---------------------------------------------------------------------------
// Launch
// ---------------------------------------------------------------------------
extern "C" void kernel_launch(void* const* d_in, const int* in_sizes, int n_in,
                              void* d_out, int out_size)
{
    const float* x        = (const float*)d_in[0];
    const float* W_in     = (const float*)d_in[1];
    const float* conv_x_w = (const float*)d_in[2];
    const float* conv_x_b = (const float*)d_in[3];
    const float* conv_z_w = (const float*)d_in[4];
    const float* conv_z_b = (const float*)d_in[5];
    const float* W_xdbl   = (const float*)d_in[6];
    const float* W_dt     = (const float*)d_in[7];
    const float* inv_dt   = (const float*)d_in[8];
    const float* Dvec     = (const float*)d_in[9];
    const float* W_out    = (const float*)d_in[10];
    const float* b_out    = (const float*)d_in[11];
    float* out            = (float*)d_out;

    float *p_xdbl, *p_delta, *p_q, *p_hs, *p_S;
    h16 *p_xzh, *p_a1h, *p_b1h, *p_xsh, *p_xsl, *p_bxh;
    h16 *p_dth, *p_dtl, *p_bdh, *p_ch, *p_b2h;
    cudaGetSymbolAddress((void**)&p_xzh,   g_xzh);
    cudaGetSymbolAddress((void**)&p_xdbl,  g_xdbl);
    cudaGetSymbolAddress((void**)&p_delta, g_delta);
    cudaGetSymbolAddress((void**)&p_q,  g_q);
    cudaGetSymbolAddress((void**)&p_hs, g_hs);
    cudaGetSymbolAddress((void**)&p_S,  g_S);
    cudaGetSymbolAddress((void**)&p_a1h, g_a1h);
    cudaGetSymbolAddress((void**)&p_b1h, g_b1h);
    cudaGetSymbolAddress((void**)&p_xsh, g_xsh); cudaGetSymbolAddress((void**)&p_xsl, g_xsl);
    cudaGetSymbolAddress((void**)&p_bxh, g_bxh);
    cudaGetSymbolAddress((void**)&p_dth, g_dth); cudaGetSymbolAddress((void**)&p_dtl, g_dtl);
    cudaGetSymbolAddress((void**)&p_bdh, g_bdh);
    cudaGetSymbolAddress((void**)&p_ch,  g_ch);
    cudaGetSymbolAddress((void**)&p_b2h, g_b2h);

    constexpr int SMEM_128 = 3 * (128 * 128 + 128 * 128) + 1024;   // 99328
    constexpr int SMEM_64  = 3 * (64 * 128 + 128 * 128) + 1024;    // 74752
    cudaFuncSetAttribute((const void*)gemm_mma<128,1,false,false,false,false,true>,
                         cudaFuncAttributeMaxDynamicSharedMemorySize, SMEM_128);
    cudaFuncSetAttribute((const void*)gemm_mma<128,1,false,true,false,false,false>,
                         cudaFuncAttributeMaxDynamicSharedMemorySize, SMEM_128);
    cudaFuncSetAttribute((const void*)gemm_mma<128,2,true,true,false,false,false>,
                         cudaFuncAttributeMaxDynamicSharedMemorySize, SMEM_128);
    cudaFuncSetAttribute((const void*)gemm_mma<64,2,false,false,true,true,false>,
                         cudaFuncAttributeMaxDynamicSharedMemorySize, SMEM_64);

    // 1) all prep in ONE launch: 4 weight transposes + x->fp16
    prep_kernel<<<4256 + 8192, 256>>>(W_in, W_xdbl, W_dt, W_out, x,
                                      p_b1h, p_bxh, p_bdh, p_b2h, p_a1h);

    // 2) xz = x @ W_in                              [8192,2048]  (1-stream, fp16 out)
    gemm_mma<128,1,false,false,false,false,true><<<dim3(DINNER / 128, MROWS / 128), 256, SMEM_128>>>(
        p_a1h, nullptr, p_b1h, nullptr, nullptr, 0.0f, p_xzh, DINNER, DMODEL, DINNER,
        nullptr, nullptr);

    // 3) both depthwise convs + silu (half2-vectorized, one launch)
    conv_both_kernel<<<dim3((MROWS / 4 * DHALF / 2) / 256, 2), 256>>>(
        p_xzh, conv_x_w, conv_x_b, conv_z_w, conv_z_b, p_xsh, p_xsl, p_ch);

    // 4) x_dbl = xs @ W_xdbl  [8192,96] (2-stream, BM=64, fused dt hi/lo split)
    gemm_mma<64,2,false,false,true,true,false><<<dim3(1, MROWS / 64), 256, SMEM_64>>>(
        p_xsh, p_xsl, p_bxh, nullptr, nullptr, 0.0f, p_xdbl, XDBL_N, DHALF, XDBL_N,
        p_dth, p_dtl);

    // 5) delta = softplus(dt_low @ W_dt + 2*inv_dt) [8192,1024]
    //    (2-stream: (dt_hi+dt_lo) @ W_dt_hi)
    gemm_mma<128,2,true,true,false,false,false><<<dim3(DHALF / 128, MROWS / 128), 256, SMEM_128>>>(
        p_dth, p_dtl, p_bdh, nullptr, inv_dt, 2.0f, p_delta, DHALF, DTRANK, DHALF,
        nullptr, nullptr);

    // 6) chunk-parallel selective scan (32 chunks) -> concat left half (fp16 rn)
    scan_p1<<<dim3(NCHUNK, 8, B_SZ), 128>>>(p_delta, p_xsh, p_xdbl, p_q, p_S);
    scan_p2<<<32, 128>>>(p_q, p_S, p_hs);
    scan_p3<<<dim3(NCHUNK, 8, B_SZ), 128>>>(p_delta, p_xsh, p_xdbl, p_hs, Dvec, p_ch);

    // 7) out = [y|z] @ W_out + b_out                [8192,1024]  (1-stream)
    gemm_mma<128,1,false,true,false,false,false><<<dim3(DMODEL / 128, MROWS / 128), 256, SMEM_128>>>(
        p_ch, nullptr, p_b2h, nullptr, b_out, 1.0f, out, DMODEL, DINNER, DMODEL,
        nullptr, nullptr);
}

// round 16
// speedup vs baseline: 1.0269x; 1.0090x over previous
#include <cuda_runtime.h>
#include <cuda_fp16.h>
#include <cstdint>
#include <cstddef>

// ---------------------------------------------------------------------------
// Problem constants (MambaVisionMixer, B=4, L=2048)
// ---------------------------------------------------------------------------
#define B_SZ    4
#define LSEQ    2048
#define DMODEL  1024
#define DINNER  2048
#define DHALF   1024
#define DSTATE  16
#define DTRANK  64
#define XDBL_N  96
#define MROWS   (B_SZ*LSEQ)   // 8192
#define NCHUNK  32
#define LCHUNK  (LSEQ/NCHUNK) // 64

typedef __half h16;

// ---------------------------------------------------------------------------
// Device scratch (static __device__ arrays — no allocations)
// ---------------------------------------------------------------------------
__device__ h16   g_xzh [(size_t)MROWS * DINNER];    // xz fp16  (32 MB)
__device__ float g_xdbl [(size_t)MROWS * XDBL_N];   // 3 MB
__device__ float g_delta[(size_t)MROWS * DHALF];    // 32 MB

__device__ float g_q [(size_t)B_SZ * NCHUNK * DSTATE * DHALF];  // 8 MB
__device__ float g_hs[(size_t)B_SZ * NCHUNK * DSTATE * DHALF];  // 8 MB
__device__ float g_S [(size_t)B_SZ * NCHUNK * DHALF];           // 512 KB

__device__ h16 g_a1h[(size_t)MROWS * DMODEL];      // x (fp16 rn)
__device__ h16 g_b1h[(size_t)DINNER * DMODEL];     // W_in^T  [2048,1024]
__device__ h16 g_xsh[(size_t)MROWS * DHALF];       // xs hi
__device__ h16 g_xsl[(size_t)MROWS * DHALF];       // xs lo (xdbl path only)
__device__ h16 g_bxh[(size_t)XDBL_N * DHALF];      // W_xdbl^T [96,1024]
__device__ h16 g_dth[(size_t)MROWS * DTRANK];      // dt_low hi [8192,64]
__device__ h16 g_dtl[(size_t)MROWS * DTRANK];
__device__ h16 g_bdh[(size_t)DHALF * DTRANK];      // W_dt^T [1024,64]
__device__ h16 g_ch [(size_t)MROWS * DINNER];      // [y|z] (fp16 rn) [8192,2048]
__device__ h16 g_b2h[(size_t)DMODEL * DINNER];     // W_out^T [1024,2048]

// ---------------------------------------------------------------------------
// Helpers (sm_80-era ISA only: compiles at compute_103 non-'a' target)
// ---------------------------------------------------------------------------
__device__ __forceinline__ uint32_t smem_u32(const void* p) {
    uint32_t r;
    asm("{ .reg .u64 t; cvta.to.shared.u64 t, %1; cvt.u32.u64 %0, t; }"
        : "=r"(r) : "l"(p));
    return r;
}

#define CP16(dst, src) \
    asm volatile("cp.async.cg.shared.global [%0], [%1], 16;" \
        :: "r"(dst), "l"(src) : "memory")
#define CP16Z(dst, src, sz) \
    asm volatile("cp.async.cg.shared.global [%0], [%1], 16, %2;" \
        :: "r"(dst), "l"(src), "r"(sz) : "memory")
#define CP_COMMIT() asm volatile("cp.async.commit_group;" ::: "memory")
#define CP_WAIT2()  asm volatile("cp.async.wait_group 2;" ::: "memory")

__device__ __forceinline__ void ldsm4(uint32_t* r, uint32_t addr) {
    asm volatile("ldmatrix.sync.aligned.m8n8.x4.shared.b16 {%0,%1,%2,%3}, [%4];"
        : "=r"(r[0]), "=r"(r[1]), "=r"(r[2]), "=r"(r[3]) : "r"(addr));
}

__device__ __forceinline__ void mma16816(float* d, const uint32_t* a,
                                         const uint32_t* b) {
    asm volatile(
        "mma.sync.aligned.m16n8k16.row.col.f32.f16.f16.f32 "
        "{%0,%1,%2,%3}, {%4,%5,%6,%7}, {%8,%9}, {%0,%1,%2,%3};"
        : "+f"(d[0]), "+f"(d[1]), "+f"(d[2]), "+f"(d[3])
        : "r"(a[0]), "r"(a[1]), "r"(a[2]), "r"(a[3]), "r"(b[0]), "r"(b[1]));
}

__device__ __forceinline__ float softplus_f(float x) {
    return fmaxf(x, 0.0f) + log1pf(expf(-fabsf(x)));
}
__device__ __forceinline__ float silu_f(float x) {
    return x / (1.0f + expf(-x));
}
__device__ __forceinline__ void split_h16(float v, h16& h, h16& l) {
    h = __float2half_rn(v);
    l = __float2half_rn(v - __half2float(h));
}

// ---------------------------------------------------------------------------
// Tensor-core GEMM (mma.sync fp16, fp32 accum), extended-K streams.
//   C[M,N] = A[M,K] @ B^T   (B stored [N,K] row-major)
//   NSTREAM==1: (Ahi,Bhi)
//   NSTREAM==2: (Ahi,Bhi), (Alo,Bhi)
//   CTA BMx128, 8 warps (2x4), warp tile (BM/2)x32, BK=64,
//   3-stage cp.async pipeline.  H16OUT: write C as fp16 rn.
// ---------------------------------------------------------------------------
template <int BM, int NSTREAM, bool SOFTPLUS, bool HASBIAS, bool H16OUT>
__global__ __launch_bounds__(256, 2)
void gemm_mma(const h16* __restrict__ Ahi, const h16* __restrict__ Alo,
              const h16* __restrict__ Bhi,
              const float* __restrict__ bias, float bias_scale,
              void* __restrict__ Cout, int N, int K)
{
    constexpr int MI     = BM / 32;
    constexpr int ABYTES = BM * 128;
    constexpr int STAGE  = ABYTES + 128 * 128;
    extern __shared__ char dsm[];
    const uint32_t base = (smem_u32(dsm) + 1023u) & ~1023u;

    const int tid    = threadIdx.x;
    const int rowBlk = blockIdx.y * BM;
    const int colBlk = blockIdx.x * 128;
    const int wid    = tid >> 5;
    const int lane   = tid & 31;
    const int warp_m = wid >> 2;
    const int warp_n = wid & 3;
    const int mat    = lane >> 3;
    const int rin    = lane & 7;

    const int KC     = K / 64;
    const int CHUNKS = NSTREAM * KC;

    uint32_t offA[MI][4], offB[2][4];
    #pragma unroll
    for (int mi = 0; mi < MI; mi++)
        #pragma unroll
        for (int j = 0; j < 4; j++) {
            int row = warp_m * (BM / 2) + mi * 16 + (mat & 1) * 8 + rin;
            int c   = 2 * j + (mat >> 1);
            offA[mi][j] = row * 128 + ((c ^ (row & 7)) << 4);
        }
    #pragma unroll
    for (int bi = 0; bi < 2; bi++)
        #pragma unroll
        for (int j = 0; j < 4; j++) {
            int row = warp_n * 32 + bi * 16 + (mat >> 1) * 8 + rin;
            int c   = 2 * j + (mat & 1);
            offB[bi][j] = ABYTES + row * 128 + ((c ^ (row & 7)) << 4);
        }

    float acc[MI][4][4];
    #pragma unroll
    for (int i = 0; i < MI; i++)
        #pragma unroll
        for (int j = 0; j < 4; j++)
            #pragma unroll
            for (int q = 0; q < 4; q++) acc[i][j][q] = 0.0f;

    auto load_stage = [&](int s, int c) {
        int stream = (NSTREAM == 1) ? 0 : ((c >= KC) ? 1 : 0);
        int k0 = (c - stream * KC) * 64;
        const h16* Ap = (NSTREAM == 2 && stream == 1) ? Alo : Ahi;
        uint32_t as_ = base + s * STAGE;
        uint32_t bs_ = as_ + ABYTES;
        #pragma unroll
        for (int t = 0; t < BM / 32; t++) {
            int idx = tid + t * 256;
            int r = idx >> 3, cc = idx & 7;
            uint32_t dst = as_ + r * 128 + ((cc ^ (r & 7)) << 4);
            const char* src =
                (const char*)(Ap + (size_t)(rowBlk + r) * K + k0) + cc * 16;
            CP16(dst, src);
        }
        #pragma unroll
        for (int t = 0; t < 4; t++) {
            int idx = tid + t * 256;
            int r = idx >> 3, cc = idx & 7;
            uint32_t dst = bs_ + r * 128 + ((cc ^ (r & 7)) << 4);
            const char* src =
                (const char*)(Bhi + (size_t)(colBlk + r) * K + k0) + cc * 16;
            CP16(dst, src);
        }
    };

    #pragma unroll
    for (int s = 0; s < 3; s++) { load_stage(s, s); CP_COMMIT(); }

    int slot = 0;
    #pragma unroll 1
    for (int i = 0; i < CHUNKS; i++) {
        CP_WAIT2();
        __syncthreads();
        const uint32_t sb = base + slot * STAGE;
        #pragma unroll
        for (int j = 0; j < 4; j++) {
            uint32_t Af[MI][4];
            #pragma unroll
            for (int mi = 0; mi < MI; mi++) ldsm4(Af[mi], sb + offA[mi][j]);
            uint32_t Bf[4][2];
            #pragma unroll
            for (int bi = 0; bi < 2; bi++) {
                uint32_t r[4];
                ldsm4(r, sb + offB[bi][j]);
                Bf[bi * 2 + 0][0] = r[0]; Bf[bi * 2 + 0][1] = r[1];
                Bf[bi * 2 + 1][0] = r[2]; Bf[bi * 2 + 1][1] = r[3];
            }
            #pragma unroll
            for (int mi = 0; mi < MI; mi++)
                #pragma unroll
                for (int ni = 0; ni < 4; ni++)
                    mma16816(acc[mi][ni], Af[mi], Bf[ni]);
        }
        __syncthreads();
        if (i + 3 < CHUNKS) load_stage(slot, i + 3);
        CP_COMMIT();
        slot = (slot == 2) ? 0 : slot + 1;
    }

    // epilogue
    const int mrow = rowBlk + warp_m * (BM / 2) + (lane >> 2);
    const int ncol = colBlk + warp_n * 32 + (lane & 3) * 2;
    #pragma unroll
    for (int mi = 0; mi < MI; mi++) {
        #pragma unroll
        for (int ni = 0; ni < 4; ni++) {
            int n0 = ncol + ni * 8;
            float v0 = acc[mi][ni][0], v1 = acc[mi][ni][1];
            float v2 = acc[mi][ni][2], v3 = acc[mi][ni][3];
            if (HASBIAS) {
                float b0 = bias_scale * __ldg(bias + n0);
                float b1 = bias_scale * __ldg(bias + n0 + 1);
                v0 += b0; v1 += b1; v2 += b0; v3 += b1;
            }
            if (SOFTPLUS) {
                v0 = softplus_f(v0); v1 = softplus_f(v1);
                v2 = softplus_f(v2); v3 = softplus_f(v3);
            }
            size_t r0 = (size_t)(mrow + mi * 16) * N + n0;
            size_t r1 = (size_t)(mrow + mi * 16 + 8) * N + n0;
            if (H16OUT) {
                h16* Ch = reinterpret_cast<h16*>(Cout);
                *reinterpret_cast<__half2*>(Ch + r0) =
                    __half2(__float2half_rn(v0), __float2half_rn(v1));
                *reinterpret_cast<__half2*>(Ch + r1) =
                    __half2(__float2half_rn(v2), __float2half_rn(v3));
            } else {
                float* Cf = reinterpret_cast<float*>(Cout);
                *reinterpret_cast<float2*>(Cf + r0) = make_float2(v0, v1);
                *reinterpret_cast<float2*>(Cf + r1) = make_float2(v2, v3);
            }
        }
    }
}

// ---------------------------------------------------------------------------
// xdbl GEMM: 2-stream shared-B (R8 scheme).  BM=64, N zfilled to 128.
//   C[8192,96] = (xs_hi + xs_lo)[8192,1024] @ W_xdbl_hi^T
//   Stage = {Ahi 8KB, Alo 8KB, B 16KB}; B loaded ONCE per k-chunk, both A
//   passes reuse it.  CHUNKS = K/64 = 16 (half the serial chain of
//   extended-K).  Epilogue: write xdbl fp32 + dt cols [0,64) as fp16 hi/lo.
// ---------------------------------------------------------------------------
__global__ __launch_bounds__(256, 2)
void gemm_xdbl_sb(const h16* __restrict__ Ahi, const h16* __restrict__ Alo,
                  const h16* __restrict__ Bhi,
                  float* __restrict__ C,
                  h16* __restrict__ dth, h16* __restrict__ dtl)
{
    constexpr int BM     = 64;
    constexpr int MI     = 2;
    constexpr int ABYTES = BM * 128;                 // 8 KB per A stream
    constexpr int STAGE  = 2 * ABYTES + 128 * 128;   // 32 KB
    constexpr int K      = DHALF;
    constexpr int N      = XDBL_N;
    extern __shared__ char dsm[];
    const uint32_t base = (smem_u32(dsm) + 1023u) & ~1023u;

    const int tid    = threadIdx.x;
    const int rowBlk = blockIdx.y * BM;
    const int wid    = tid >> 5;
    const int lane   = tid & 31;
    const int warp_m = wid >> 2;
    const int warp_n = wid & 3;
    const int mat    = lane >> 3;
    const int rin    = lane & 7;

    const int CHUNKS = K / 64;                       // 16

    uint32_t offA[MI][4], offB[2][4];
    #pragma unroll
    for (int mi = 0; mi < MI; mi++)
        #pragma unroll
        for (int j = 0; j < 4; j++) {
            int row = warp_m * 32 + mi * 16 + (mat & 1) * 8 + rin;
            int c   = 2 * j + (mat >> 1);
            offA[mi][j] = row * 128 + ((c ^ (row & 7)) << 4);
        }
    #pragma unroll
    for (int bi = 0; bi < 2; bi++)
        #pragma unroll
        for (int j = 0; j < 4; j++) {
            int row = warp_n * 32 + bi * 16 + (mat >> 1) * 8 + rin;
            int c   = 2 * j + (mat & 1);
            offB[bi][j] = 2 * ABYTES + row * 128 + ((c ^ (row & 7)) << 4);
        }

    float acc[MI][4][4];
    #pragma unroll
    for (int i = 0; i < MI; i++)
        #pragma unroll
        for (int j = 0; j < 4; j++)
            #pragma unroll
            for (int q = 0; q < 4; q++) acc[i][j][q] = 0.0f;

    auto load_stage = [&](int s, int c) {
        int k0 = c * 64;
        uint32_t st = base + s * STAGE;
        #pragma unroll
        for (int t = 0; t < 2; t++) {               // 64 rows x 8 chunks, both A
            int idx = tid + t * 256;
            int r = idx >> 3, cc = idx & 7;
            uint32_t sw = r * 128 + ((cc ^ (r & 7)) << 4);
            const char* srcH =
                (const char*)(Ahi + (size_t)(rowBlk + r) * K + k0) + cc * 16;
            const char* srcL =
                (const char*)(Alo + (size_t)(rowBlk + r) * K + k0) + cc * 16;
            CP16(st + sw, srcH);
            CP16(st + ABYTES + sw, srcL);
        }
        #pragma unroll
        for (int t = 0; t < 4; t++) {               // B: 128 rows (zfill > 95)
            int idx = tid + t * 256;
            int r = idx >> 3, cc = idx & 7;
            uint32_t sw = r * 128 + ((cc ^ (r & 7)) << 4);
            int ok = (r < XDBL_N);
            const char* src =
                (const char*)(Bhi + (size_t)(ok ? r : 0) * K + k0) + cc * 16;
            CP16Z(st + 2 * ABYTES + sw, src, ok ? 16u : 0u);
        }
    };

    #pragma unroll
    for (int s = 0; s < 3; s++) { load_stage(s, s); CP_COMMIT(); }

    int slot = 0;
    #pragma unroll 1
    for (int i = 0; i < CHUNKS; i++) {
        CP_WAIT2();
        __syncthreads();
        const uint32_t sb = base + slot * STAGE;
        #pragma unroll
        for (int pass = 0; pass < 2; pass++) {       // A-hi then A-lo, same B
            const uint32_t ab = sb + pass * ABYTES;
            #pragma unroll
            for (int j = 0; j < 4; j++) {
                uint32_t Af[MI][4];
                #pragma unroll
                for (int mi = 0; mi < MI; mi++) ldsm4(Af[mi], ab + offA[mi][j]);
                uint32_t Bf[4][2];
                #pragma unroll
                for (int bi = 0; bi < 2; bi++) {
                    uint32_t r[4];
                    ldsm4(r, sb + offB[bi][j]);
                    Bf[bi * 2 + 0][0] = r[0]; Bf[bi * 2 + 0][1] = r[1];
                    Bf[bi * 2 + 1][0] = r[2]; Bf[bi * 2 + 1][1] = r[3];
                }
                #pragma unroll
                for (int mi = 0; mi < MI; mi++)
                    #pragma unroll
                    for (int ni = 0; ni < 4; ni++)
                        mma16816(acc[mi][ni], Af[mi], Bf[ni]);
            }
        }
        __syncthreads();
        if (i + 3 < CHUNKS) load_stage(slot, i + 3);
        CP_COMMIT();
        slot = (slot == 2) ? 0 : slot + 1;
    }

    // epilogue (N=96 bound check; dt split for cols [0,64))
    const int mrow = rowBlk + warp_m * 32 + (lane >> 2);
    const int ncol = warp_n * 32 + (lane & 3) * 2;
    #pragma unroll
    for (int mi = 0; mi < MI; mi++) {
        #pragma unroll
        for (int ni = 0; ni < 4; ni++) {
            int n0 = ncol + ni * 8;
            if (n0 >= XDBL_N) continue;
            float v0 = acc[mi][ni][0], v1 = acc[mi][ni][1];
            float v2 = acc[mi][ni][2], v3 = acc[mi][ni][3];
            size_t r0 = (size_t)(mrow + mi * 16) * N + n0;
            size_t r1 = (size_t)(mrow + mi * 16 + 8) * N + n0;
            *reinterpret_cast<float2*>(C + r0) = make_float2(v0, v1);
            *reinterpret_cast<float2*>(C + r1) = make_float2(v2, v3);
            if (n0 < DTRANK) {
                h16 hh, ll;
                size_t d0 = (size_t)(mrow + mi * 16) * DTRANK + n0;
                size_t d1 = (size_t)(mrow + mi * 16 + 8) * DTRANK + n0;
                split_h16(v0, hh, ll); dth[d0] = hh;     dtl[d0] = ll;
                split_h16(v1, hh, ll); dth[d0 + 1] = hh; dtl[d0 + 1] = ll;
                split_h16(v2, hh, ll); dth[d1] = hh;     dtl[d1] = ll;
                split_h16(v3, hh, ll); dth[d1 + 1] = hh; dtl[d1 + 1] = ll;
            }
        }
    }
}

// ---------------------------------------------------------------------------
// Combined prep — ONE launch: 4 weight transposes AND x -> fp16.
// ---------------------------------------------------------------------------
__global__ __launch_bounds__(256)
void prep_kernel(const float* __restrict__ W_in,
                 const float* __restrict__ W_xdbl,
                 const float* __restrict__ W_dt,
                 const float* __restrict__ W_out,
                 const float* __restrict__ x,
                 h16* __restrict__ b1h, h16* __restrict__ bxh,
                 h16* __restrict__ bdh,
                 h16* __restrict__ b2h, h16* __restrict__ a1h)
{
    int blk = blockIdx.x;
    if (blk >= 4256) {
        int i = (blk - 4256) * 1024 + threadIdx.x * 4;
        float4 v = *reinterpret_cast<const float4*>(x + i);
        __half2* ph = reinterpret_cast<__half2*>(a1h + i);
        ph[0] = __half2(__float2half_rn(v.x), __float2half_rn(v.y));
        ph[1] = __half2(__float2half_rn(v.z), __float2half_rn(v.w));
        return;
    }

    __shared__ float t[32][33];
    const float* in;
    h16 *oh;
    int R, C, bx, by;
    if (blk < 2048)      { in = W_in;   oh = b1h; R = 1024; C = 2048; bx = blk % 64; by = blk / 64; }
    else if (blk < 2144) { blk -= 2048; in = W_xdbl; oh = bxh; R = 1024; C = 96;   bx = blk % 3;  by = blk / 3; }
    else if (blk < 2208) { blk -= 2144; in = W_dt;  oh = bdh; R = 64; C = 1024; bx = blk % 32; by = blk / 32; }
    else                 { blk -= 2208; in = W_out; oh = b2h; R = 2048; C = 1024; bx = blk % 32; by = blk / 32; }

    const int cx = bx * 32, ry = by * 32;
    const int tx = threadIdx.x & 31, ty = threadIdx.x >> 5;   // 32 x 8
    #pragma unroll
    for (int j = ty; j < 32; j += 8)
        t[j][tx] = in[(size_t)(ry + j) * C + cx + tx];
    __syncthreads();
    #pragma unroll
    for (int j = ty; j < 32; j += 8) {
        float v = t[tx][j];
        size_t o = (size_t)(cx + j) * R + ry + tx;
        oh[o] = __float2half_rn(v);
    }
}

// ---------------------------------------------------------------------------
// Depthwise conv (k=4, SAME: pad left 1, right 2) + SiLU over BOTH halves,
// half2-vectorized: each thread handles 2 channels x 4 consecutive l outputs.
// ---------------------------------------------------------------------------
__global__ __launch_bounds__(256)
void conv_both_kernel(const h16* __restrict__ xz,
                      const float* __restrict__ wx, const float* __restrict__ bx,
                      const float* __restrict__ wz, const float* __restrict__ bz,
                      h16* __restrict__ xsh, h16* __restrict__ xsl,
                      h16* __restrict__ ch)
{
    const int half = blockIdx.y;
    const float* w    = half ? wz : wx;
    const float* bias = half ? bz : bx;
    const int col0 = half ? DHALF : 0;

    int idx = blockIdx.x * blockDim.x + threadIdx.x;   // < MROWS/4 * DHALF/2
    int c2  = (idx & 511) << 1;
    int bl4 = idx >> 9;
    int b   = bl4 >> 9;
    int l0  = (bl4 & 511) << 2;

    float2 w0 = *reinterpret_cast<const float2*>(w + c2);
    float2 w1 = *reinterpret_cast<const float2*>(w + DHALF + c2);
    float2 w2 = *reinterpret_cast<const float2*>(w + 2 * DHALF + c2);
    float2 w3 = *reinterpret_cast<const float2*>(w + 3 * DHALF + c2);
    float2 bv = *reinterpret_cast<const float2*>(bias + c2);

    const __half2* src = reinterpret_cast<const __half2*>(
        xz + (size_t)b * LSEQ * DINNER + col0 + c2);
    float2 win[7];
    #pragma unroll
    for (int j = 0; j < 7; j++) {
        int l = l0 + j - 1;
        win[j] = (l >= 0 && l < LSEQ)
                 ? __half22float2(src[(size_t)l * (DINNER / 2)])
                 : make_float2(0.0f, 0.0f);
    }

    #pragma unroll
    for (int k = 0; k < 4; k++) {
        float ax = bv.x, ay = bv.y;
        ax = fmaf(win[k].x,     w0.x, ax); ay = fmaf(win[k].y,     w0.y, ay);
        ax = fmaf(win[k + 1].x, w1.x, ax); ay = fmaf(win[k + 1].y, w1.y, ay);
        ax = fmaf(win[k + 2].x, w2.x, ax); ay = fmaf(win[k + 2].y, w2.y, ay);
        ax = fmaf(win[k + 3].x, w3.x, ax); ay = fmaf(win[k + 3].y, w3.y, ay);
        float vx = silu_f(ax), vy = silu_f(ay);
        size_t row = (size_t)b * LSEQ + l0 + k;
        if (half == 0) {
            h16 hx, lx, hy, ly;
            split_h16(vx, hx, lx); split_h16(vy, hy, ly);
            size_t o = row * DHALF + c2;
            *reinterpret_cast<__half2*>(xsh + o) = __half2(hx, hy);
            *reinterpret_cast<__half2*>(xsl + o) = __half2(lx, ly);
        } else {
            *reinterpret_cast<__half2*>(ch + row * DINNER + DHALF + c2) =
                __half2(__float2half_rn(vx), __float2half_rn(vy));
        }
    }
}

// ---------------------------------------------------------------------------
// Chunk-parallel selective scan.  A[d][n] = -(n+1) => dA_n = exp(-delta)^(n+1).
//   NCHUNK=32, LCHUNK=64 -> 1024 blocks in phases 1 and 3.
// u is read hi-only (fp16 rn).
// ---------------------------------------------------------------------------
#define PW16(p1, pw)                                                    \
    float p2 = (p1) * (p1), p3 = p2 * (p1), p4 = p2 * p2;               \
    float p5 = p4 * (p1), p6 = p4 * p2, p7 = p4 * p3, p8 = p4 * p4;     \
    float pw[16] = {(p1), p2, p3, p4, p5, p6, p7, p8,                   \
                    p8 * (p1), p8 * p2, p8 * p3, p8 * p4,               \
                    p8 * p5, p8 * p6, p8 * p7, p8 * p8};

__global__ __launch_bounds__(128)
void scan_p1(const float* __restrict__ delta,
             const h16* __restrict__ uh,
             const float* __restrict__ xdbl,
             float* __restrict__ q, float* __restrict__ S)
{
    const int tid = threadIdx.x;
    const int chunk = blockIdx.x, dblk = blockIdx.y, b = blockIdx.z;
    const int d = (dblk << 7) + tid;

    __shared__ float sB[16][DSTATE];
    __shared__ float sd[16][128];
    __shared__ float su[16][128];

    float h[DSTATE];
    #pragma unroll
    for (int n = 0; n < DSTATE; n++) h[n] = 0.0f;
    float sum = 0.0f;
    const size_t baseRow = (size_t)b * LSEQ + (size_t)chunk * LCHUNK;

    for (int t0 = 0; t0 < LCHUNK; t0 += 16) {
        {
            int s = tid >> 3;
            int i = (tid & 7) << 1;
            float2 v = *reinterpret_cast<const float2*>(
                xdbl + (baseRow + t0 + s) * XDBL_N + DTRANK + i);
            sB[s][i] = v.x; sB[s][i + 1] = v.y;
        }
        #pragma unroll
        for (int s = 0; s < 16; s++) {
            size_t r = (baseRow + t0 + s) * DHALF + d;
            sd[s][tid] = delta[r];
            su[s][tid] = __half2float(uh[r]);
        }
        __syncthreads();

        #pragma unroll
        for (int s = 0; s < 16; s++) {
            float dl = sd[s][tid];
            float du = dl * su[s][tid];
            sum += dl;
            float p1 = __expf(-dl);
            PW16(p1, pw)
            #pragma unroll
            for (int n = 0; n < DSTATE; n++)
                h[n] = fmaf(pw[n], h[n], du * sB[s][n]);
        }
        __syncthreads();
    }
    const size_t cbase = ((size_t)(b * NCHUNK + chunk) * DSTATE) * DHALF + d;
    #pragma unroll
    for (int n = 0; n < DSTATE; n++) q[cbase + (size_t)n * DHALF] = h[n];
    S[(size_t)(b * NCHUNK + chunk) * DHALF + d] = sum;
}

__global__ __launch_bounds__(128)
void scan_p2(const float* __restrict__ q, const float* __restrict__ S,
             float* __restrict__ hs)
{
    const int idx = blockIdx.x * 128 + threadIdx.x;   // < 4096
    const int b = idx >> 10, d = idx & (DHALF - 1);
    float h[DSTATE];
    #pragma unroll
    for (int n = 0; n < DSTATE; n++) h[n] = 0.0f;
    for (int c = 0; c < NCHUNK; c++) {
        const size_t cbase = ((size_t)(b * NCHUNK + c) * DSTATE) * DHALF + d;
        #pragma unroll
        for (int n = 0; n < DSTATE; n++) hs[cbase + (size_t)n * DHALF] = h[n];
        float s = S[(size_t)(b * NCHUNK + c) * DHALF + d];
        float p1 = __expf(-s);
        PW16(p1, pw)
        #pragma unroll
        for (int n = 0; n < DSTATE; n++)
            h[n] = fmaf(pw[n], h[n], q[cbase + (size_t)n * DHALF]);
    }
}

__global__ __launch_bounds__(128)
void scan_p3(const float* __restrict__ delta,
             const h16* __restrict__ uh,
             const float* __restrict__ xdbl, const float* __restrict__ hs,
             const float* __restrict__ Dv,
             h16* __restrict__ cat_h)
{
    const int tid = threadIdx.x;
    const int chunk = blockIdx.x, dblk = blockIdx.y, b = blockIdx.z;
    const int d = (dblk << 7) + tid;

    __shared__ float sB[16][DSTATE];
    __shared__ float sC[16][DSTATE];
    __shared__ float sd[16][128];
    __shared__ float su[16][128];

    float h[DSTATE];
    const size_t cbase = ((size_t)(b * NCHUNK + chunk) * DSTATE) * DHALF + d;
    #pragma unroll
    for (int n = 0; n < DSTATE; n++) h[n] = hs[cbase + (size_t)n * DHALF];
    const float Dd = Dv[d];
    const size_t baseRow = (size_t)b * LSEQ + (size_t)chunk * LCHUNK;

    for (int t0 = 0; t0 < LCHUNK; t0 += 16) {
        {
            int s = tid >> 3;
            int i = (tid & 7) << 2;
            float4 v = *reinterpret_cast<const float4*>(
                xdbl + (baseRow + t0 + s) * XDBL_N + DTRANK + i);
            float vv[4] = {v.x, v.y, v.z, v.w};
            #pragma unroll
            for (int qq = 0; qq < 4; qq++) {
                int ii = i + qq;
                if (ii < DSTATE) sB[s][ii] = vv[qq];
                else             sC[s][ii - DSTATE] = vv[qq];
            }
        }
        #pragma unroll
        for (int s = 0; s < 16; s++) {
            size_t r = (baseRow + t0 + s) * DHALF + d;
            sd[s][tid] = delta[r];
            su[s][tid] = __half2float(uh[r]);
        }
        __syncthreads();

        #pragma unroll
        for (int s = 0; s < 16; s++) {
            float dl = sd[s][tid];
            float uu = su[s][tid];
            float du = dl * uu;
            float p1 = __expf(-dl);
            PW16(p1, pw)
            float y0 = 0.f, y1 = 0.f, y2 = 0.f, y3 = 0.f;
            #pragma unroll
            for (int n = 0; n < DSTATE; n += 4) {
                h[n + 0] = fmaf(pw[n + 0], h[n + 0], du * sB[s][n + 0]);
                h[n + 1] = fmaf(pw[n + 1], h[n + 1], du * sB[s][n + 1]);
                h[n + 2] = fmaf(pw[n + 2], h[n + 2], du * sB[s][n + 2]);
                h[n + 3] = fmaf(pw[n + 3], h[n + 3], du * sB[s][n + 3]);
                y0 = fmaf(h[n + 0], sC[s][n + 0], y0);
                y1 = fmaf(h[n + 1], sC[s][n + 1], y1);
                y2 = fmaf(h[n + 2], sC[s][n + 2], y2);
                y3 = fmaf(h[n + 3], sC[s][n + 3], y3);
            }
            float yv = fmaf(uu, Dd, (y0 + y1) + (y2 + y3));
            cat_h[(baseRow + t0 + s) * DINNER + d] = __float2half_rn(yv);
        }
        __syncthreads();
    }
}

// ---------------------------------------------------------------------------
// Launch
// ---------------------------------------------------------------------------
extern "C" void kernel_launch(void* const* d_in, const int* in_sizes, int n_in,
                              void* d_out, int out_size)
{
    const float* x        = (const float*)d_in[0];
    const float* W_in     = (const float*)d_in[1];
    const float* conv_x_w = (const float*)d_in[2];
    const float* conv_x_b = (const float*)d_in[3];
    const float* conv_z_w = (const float*)d_in[4];
    const float* conv_z_b = (const float*)d_in[5];
    const float* W_xdbl   = (const float*)d_in[6];
    const float* W_dt     = (const float*)d_in[7];
    const float* inv_dt   = (const float*)d_in[8];
    const float* Dvec     = (const float*)d_in[9];
    const float* W_out    = (const float*)d_in[10];
    const float* b_out    = (const float*)d_in[11];
    float* out            = (float*)d_out;

    float *p_xdbl, *p_delta, *p_q, *p_hs, *p_S;
    h16 *p_xzh, *p_a1h, *p_b1h, *p_xsh, *p_xsl, *p_bxh;
    h16 *p_dth, *p_dtl, *p_bdh, *p_ch, *p_b2h;
    cudaGetSymbolAddress((void**)&p_xzh,   g_xzh);
    cudaGetSymbolAddress((void**)&p_xdbl,  g_xdbl);
    cudaGetSymbolAddress((void**)&p_delta, g_delta);
    cudaGetSymbolAddress((void**)&p_q,  g_q);
    cudaGetSymbolAddress((void**)&p_hs, g_hs);
    cudaGetSymbolAddress((void**)&p_S,  g_S);
    cudaGetSymbolAddress((void**)&p_a1h, g_a1h);
    cudaGetSymbolAddress((void**)&p_b1h, g_b1h);
    cudaGetSymbolAddress((void**)&p_xsh, g_xsh); cudaGetSymbolAddress((void**)&p_xsl, g_xsl);
    cudaGetSymbolAddress((void**)&p_bxh, g_bxh);
    cudaGetSymbolAddress((void**)&p_dth, g_dth); cudaGetSymbolAddress((void**)&p_dtl, g_dtl);
    cudaGetSymbolAddress((void**)&p_bdh, g_bdh);
    cudaGetSymbolAddress((void**)&p_ch,  g_ch);
    cudaGetSymbolAddress((void**)&p_b2h, g_b2h);

    constexpr int SMEM_128 = 3 * (128 * 128 + 128 * 128) + 1024;   // 99328
    constexpr int SMEM_SB  = 3 * (2 * 64 * 128 + 128 * 128) + 1024; // 99328
    cudaFuncSetAttribute((const void*)gemm_mma<128,1,false,false,true>,
                         cudaFuncAttributeMaxDynamicSharedMemorySize, SMEM_128);
    cudaFuncSetAttribute((const void*)gemm_mma<128,1,false,true,false>,
                         cudaFuncAttributeMaxDynamicSharedMemorySize, SMEM_128);
    cudaFuncSetAttribute((const void*)gemm_mma<128,2,true,true,false>,
                         cudaFuncAttributeMaxDynamicSharedMemorySize, SMEM_128);
    cudaFuncSetAttribute((const void*)gemm_xdbl_sb,
                         cudaFuncAttributeMaxDynamicSharedMemorySize, SMEM_SB);

    // 1) all prep in ONE launch: 4 weight transposes + x->fp16
    prep_kernel<<<4256 + 8192, 256>>>(W_in, W_xdbl, W_dt, W_out, x,
                                      p_b1h, p_bxh, p_bdh, p_b2h, p_a1h);

    // 2) xz = x @ W_in                              [8192,2048]  (1-stream, fp16 out)
    gemm_mma<128,1,false,false,true><<<dim3(DINNER / 128, MROWS / 128), 256, SMEM_128>>>(
        p_a1h, nullptr, p_b1h, nullptr, 0.0f, p_xzh, DINNER, DMODEL);

    // 3) both depthwise convs + silu (half2-vectorized, one launch)
    conv_both_kernel<<<dim3((MROWS / 4 * DHALF / 2) / 256, 2), 256>>>(
        p_xzh, conv_x_w, conv_x_b, conv_z_w, conv_z_b, p_xsh, p_xsl, p_ch);

    // 4) x_dbl = xs @ W_xdbl  [8192,96] (2-stream shared-B, 16-chunk chain)
    gemm_xdbl_sb<<<dim3(1, MROWS / 64), 256, SMEM_SB>>>(
        p_xsh, p_xsl, p_bxh, p_xdbl, p_dth, p_dtl);

    // 5) delta = softplus(dt_low @ W_dt + 2*inv_dt) [8192,1024]
    //    (2-stream: (dt_hi+dt_lo) @ W_dt_hi)
    gemm_mma<128,2,true,true,false><<<dim3(DHALF / 128, MROWS / 128), 256, SMEM_128>>>(
        p_dth, p_dtl, p_bdh, inv_dt, 2.0f, p_delta, DHALF, DTRANK);

    // 6) chunk-parallel selective scan (32 chunks) -> concat left half (fp16 rn)
    scan_p1<<<dim3(NCHUNK, 8, B_SZ), 128>>>(p_delta, p_xsh, p_xdbl, p_q, p_S);
    scan_p2<<<32, 128>>>(p_q, p_S, p_hs);
    scan_p3<<<dim3(NCHUNK, 8, B_SZ), 128>>>(p_delta, p_xsh, p_xdbl, p_hs, Dvec, p_ch);

    // 7) out = [y|z] @ W_out + b_out                [8192,1024]  (1-stream)
    gemm_mma<128,1,false,true,false><<<dim3(DMODEL / 128, MROWS / 128), 256, SMEM_128>>>(
        p_ch, nullptr, p_b2h, b_out, 1.0f, out, DMODEL, DINNER);
}

// round 17
// speedup vs baseline: 1.0290x; 1.0020x over previous
#include <cuda_runtime.h>
#include <cuda_fp16.h>
#include <cstdint>
#include <cstddef>

// ---------------------------------------------------------------------------
// Problem constants (MambaVisionMixer, B=4, L=2048)
// ---------------------------------------------------------------------------
#define B_SZ    4
#define LSEQ    2048
#define DMODEL  1024
#define DINNER  2048
#define DHALF   1024
#define DSTATE  16
#define DTRANK  64
#define XDBL_N  96
#define MROWS   (B_SZ*LSEQ)   // 8192
#define NCHUNK  32
#define LCHUNK  (LSEQ/NCHUNK) // 64

typedef __half h16;

// ---------------------------------------------------------------------------
// Device scratch (static __device__ arrays — no allocations)
// ---------------------------------------------------------------------------
__device__ h16   g_xzh [(size_t)MROWS * DINNER];    // xz fp16  (32 MB)
__device__ float g_xdbl [(size_t)MROWS * XDBL_N];   // 3 MB
__device__ float g_delta[(size_t)MROWS * DHALF];    // 32 MB

__device__ float g_q [(size_t)B_SZ * NCHUNK * DSTATE * DHALF];  // 8 MB
__device__ float g_hs[(size_t)B_SZ * NCHUNK * DSTATE * DHALF];  // 8 MB
__device__ float g_S [(size_t)B_SZ * NCHUNK * DHALF];           // 512 KB

__device__ h16 g_a1h[(size_t)MROWS * DMODEL];      // x (fp16 rn)
__device__ h16 g_b1h[(size_t)DINNER * DMODEL];     // W_in^T  [2048,1024]
__device__ h16 g_xsh[(size_t)MROWS * DHALF];       // xs hi
__device__ h16 g_xsl[(size_t)MROWS * DHALF];       // xs lo (xdbl path only)
__device__ h16 g_bxh[(size_t)XDBL_N * DHALF];      // W_xdbl^T [96,1024]
__device__ h16 g_dth[(size_t)MROWS * DTRANK];      // dt_low hi [8192,64]
__device__ h16 g_dtl[(size_t)MROWS * DTRANK];
__device__ h16 g_bdh[(size_t)DHALF * DTRANK];      // W_dt^T [1024,64]
__device__ h16 g_ch [(size_t)MROWS * DINNER];      // [y|z] (fp16 rn) [8192,2048]
__device__ h16 g_b2h[(size_t)DMODEL * DINNER];     // W_out^T [1024,2048]

// ---------------------------------------------------------------------------
// Helpers (sm_80-era ISA only: compiles at compute_103 non-'a' target)
// ---------------------------------------------------------------------------
__device__ __forceinline__ uint32_t smem_u32(const void* p) {
    uint32_t r;
    asm("{ .reg .u64 t; cvta.to.shared.u64 t, %1; cvt.u32.u64 %0, t; }"
        : "=r"(r) : "l"(p));
    return r;
}

#define CP16(dst, src) \
    asm volatile("cp.async.cg.shared.global [%0], [%1], 16;" \
        :: "r"(dst), "l"(src) : "memory")
#define CP16Z(dst, src, sz) \
    asm volatile("cp.async.cg.shared.global [%0], [%1], 16, %2;" \
        :: "r"(dst), "l"(src), "r"(sz) : "memory")
#define CP_COMMIT() asm volatile("cp.async.commit_group;" ::: "memory")
#define CP_WAIT2()  asm volatile("cp.async.wait_group 2;" ::: "memory")

__device__ __forceinline__ void ldsm4(uint32_t* r, uint32_t addr) {
    asm volatile("ldmatrix.sync.aligned.m8n8.x4.shared.b16 {%0,%1,%2,%3}, [%4];"
        : "=r"(r[0]), "=r"(r[1]), "=r"(r[2]), "=r"(r[3]) : "r"(addr));
}

__device__ __forceinline__ void mma16816(float* d, const uint32_t* a,
                                         const uint32_t* b) {
    asm volatile(
        "mma.sync.aligned.m16n8k16.row.col.f32.f16.f16.f32 "
        "{%0,%1,%2,%3}, {%4,%5,%6,%7}, {%8,%9}, {%0,%1,%2,%3};"
        : "+f"(d[0]), "+f"(d[1]), "+f"(d[2]), "+f"(d[3])
        : "r"(a[0]), "r"(a[1]), "r"(a[2]), "r"(a[3]), "r"(b[0]), "r"(b[1]));
}

__device__ __forceinline__ float softplus_f(float x) {
    return fmaxf(x, 0.0f) + log1pf(expf(-fabsf(x)));
}
__device__ __forceinline__ float silu_f(float x) {
    return x / (1.0f + expf(-x));
}
__device__ __forceinline__ void split_h16(float v, h16& h, h16& l) {
    h = __float2half_rn(v);
    l = __float2half_rn(v - __half2float(h));
}

// ---------------------------------------------------------------------------
// Tensor-core GEMM (mma.sync fp16, fp32 accum), extended-K streams.
//   C[M,N] = A[M,K] @ B^T   (B stored [N,K] row-major)
//   NSTREAM==1: (Ahi,Bhi)
//   NSTREAM==2: (Ahi,Bhi), (Alo,Bhi)
//   CTA BMx128, 8 warps (2x4), warp tile (BM/2)x32, BK=64,
//   3-stage cp.async pipeline.  H16OUT: write C as fp16 rn.
// ---------------------------------------------------------------------------
template <int BM, int NSTREAM, bool SOFTPLUS, bool HASBIAS, bool H16OUT>
__global__ __launch_bounds__(256, 2)
void gemm_mma(const h16* __restrict__ Ahi, const h16* __restrict__ Alo,
              const h16* __restrict__ Bhi,
              const float* __restrict__ bias, float bias_scale,
              void* __restrict__ Cout, int N, int K)
{
    constexpr int MI     = BM / 32;
    constexpr int ABYTES = BM * 128;
    constexpr int STAGE  = ABYTES + 128 * 128;
    extern __shared__ char dsm[];
    const uint32_t base = (smem_u32(dsm) + 1023u) & ~1023u;

    const int tid    = threadIdx.x;
    const int rowBlk = blockIdx.y * BM;
    const int colBlk = blockIdx.x * 128;
    const int wid    = tid >> 5;
    const int lane   = tid & 31;
    const int warp_m = wid >> 2;
    const int warp_n = wid & 3;
    const int mat    = lane >> 3;
    const int rin    = lane & 7;

    const int KC     = K / 64;
    const int CHUNKS = NSTREAM * KC;

    uint32_t offA[MI][4], offB[2][4];
    #pragma unroll
    for (int mi = 0; mi < MI; mi++)
        #pragma unroll
        for (int j = 0; j < 4; j++) {
            int row = warp_m * (BM / 2) + mi * 16 + (mat & 1) * 8 + rin;
            int c   = 2 * j + (mat >> 1);
            offA[mi][j] = row * 128 + ((c ^ (row & 7)) << 4);
        }
    #pragma unroll
    for (int bi = 0; bi < 2; bi++)
        #pragma unroll
        for (int j = 0; j < 4; j++) {
            int row = warp_n * 32 + bi * 16 + (mat >> 1) * 8 + rin;
            int c   = 2 * j + (mat & 1);
            offB[bi][j] = ABYTES + row * 128 + ((c ^ (row & 7)) << 4);
        }

    float acc[MI][4][4];
    #pragma unroll
    for (int i = 0; i < MI; i++)
        #pragma unroll
        for (int j = 0; j < 4; j++)
            #pragma unroll
            for (int q = 0; q < 4; q++) acc[i][j][q] = 0.0f;

    auto load_stage = [&](int s, int c) {
        int stream = (NSTREAM == 1) ? 0 : ((c >= KC) ? 1 : 0);
        int k0 = (c - stream * KC) * 64;
        const h16* Ap = (NSTREAM == 2 && stream == 1) ? Alo : Ahi;
        uint32_t as_ = base + s * STAGE;
        uint32_t bs_ = as_ + ABYTES;
        #pragma unroll
        for (int t = 0; t < BM / 32; t++) {
            int idx = tid + t * 256;
            int r = idx >> 3, cc = idx & 7;
            uint32_t dst = as_ + r * 128 + ((cc ^ (r & 7)) << 4);
            const char* src =
                (const char*)(Ap + (size_t)(rowBlk + r) * K + k0) + cc * 16;
            CP16(dst, src);
        }
        #pragma unroll
        for (int t = 0; t < 4; t++) {
            int idx = tid + t * 256;
            int r = idx >> 3, cc = idx & 7;
            uint32_t dst = bs_ + r * 128 + ((cc ^ (r & 7)) << 4);
            const char* src =
                (const char*)(Bhi + (size_t)(colBlk + r) * K + k0) + cc * 16;
            CP16(dst, src);
        }
    };

    #pragma unroll
    for (int s = 0; s < 3; s++) { load_stage(s, s); CP_COMMIT(); }

    int slot = 0;
    #pragma unroll 1
    for (int i = 0; i < CHUNKS; i++) {
        CP_WAIT2();
        __syncthreads();
        const uint32_t sb = base + slot * STAGE;
        #pragma unroll
        for (int j = 0; j < 4; j++) {
            uint32_t Af[MI][4];
            #pragma unroll
            for (int mi = 0; mi < MI; mi++) ldsm4(Af[mi], sb + offA[mi][j]);
            uint32_t Bf[4][2];
            #pragma unroll
            for (int bi = 0; bi < 2; bi++) {
                uint32_t r[4];
                ldsm4(r, sb + offB[bi][j]);
                Bf[bi * 2 + 0][0] = r[0]; Bf[bi * 2 + 0][1] = r[1];
                Bf[bi * 2 + 1][0] = r[2]; Bf[bi * 2 + 1][1] = r[3];
            }
            #pragma unroll
            for (int mi = 0; mi < MI; mi++)
                #pragma unroll
                for (int ni = 0; ni < 4; ni++)
                    mma16816(acc[mi][ni], Af[mi], Bf[ni]);
        }
        __syncthreads();
        if (i + 3 < CHUNKS) load_stage(slot, i + 3);
        CP_COMMIT();
        slot = (slot == 2) ? 0 : slot + 1;
    }

    // epilogue
    const int mrow = rowBlk + warp_m * (BM / 2) + (lane >> 2);
    const int ncol = colBlk + warp_n * 32 + (lane & 3) * 2;
    #pragma unroll
    for (int mi = 0; mi < MI; mi++) {
        #pragma unroll
        for (int ni = 0; ni < 4; ni++) {
            int n0 = ncol + ni * 8;
            float v0 = acc[mi][ni][0], v1 = acc[mi][ni][1];
            float v2 = acc[mi][ni][2], v3 = acc[mi][ni][3];
            if (HASBIAS) {
                float b0 = bias_scale * __ldg(bias + n0);
                float b1 = bias_scale * __ldg(bias + n0 + 1);
                v0 += b0; v1 += b1; v2 += b0; v3 += b1;
            }
            if (SOFTPLUS) {
                v0 = softplus_f(v0); v1 = softplus_f(v1);
                v2 = softplus_f(v2); v3 = softplus_f(v3);
            }
            size_t r0 = (size_t)(mrow + mi * 16) * N + n0;
            size_t r1 = (size_t)(mrow + mi * 16 + 8) * N + n0;
            if (H16OUT) {
                h16* Ch = reinterpret_cast<h16*>(Cout);
                *reinterpret_cast<__half2*>(Ch + r0) =
                    __half2(__float2half_rn(v0), __float2half_rn(v1));
                *reinterpret_cast<__half2*>(Ch + r1) =
                    __half2(__float2half_rn(v2), __float2half_rn(v3));
            } else {
                float* Cf = reinterpret_cast<float*>(Cout);
                *reinterpret_cast<float2*>(Cf + r0) = make_float2(v0, v1);
                *reinterpret_cast<float2*>(Cf + r1) = make_float2(v2, v3);
            }
        }
    }
}

// ---------------------------------------------------------------------------
// xdbl GEMM: 2-stream shared-B, BM=32 (grid 256 -> all SMs busy).
//   C[8192,96] = (xs_hi + xs_lo)[8192,1024] @ W_xdbl_hi^T
//   Stage = {Ahi 4KB, Alo 4KB, B 16KB} = 24KB; 3 stages = 72KB.
//   B loaded ONCE per k-chunk, both A passes reuse it.  CHUNKS = 16.
//   Epilogue: write xdbl fp32 + dt cols [0,64) as fp16 hi/lo.
// ---------------------------------------------------------------------------
__global__ __launch_bounds__(256, 2)
void gemm_xdbl_sb(const h16* __restrict__ Ahi, const h16* __restrict__ Alo,
                  const h16* __restrict__ Bhi,
                  float* __restrict__ C,
                  h16* __restrict__ dth, h16* __restrict__ dtl)
{
    constexpr int BM     = 32;
    constexpr int ABYTES = BM * 128;                 // 4 KB per A stream
    constexpr int STAGE  = 2 * ABYTES + 128 * 128;   // 24 KB
    constexpr int K      = DHALF;
    constexpr int N      = XDBL_N;
    extern __shared__ char dsm[];
    const uint32_t base = (smem_u32(dsm) + 1023u) & ~1023u;

    const int tid    = threadIdx.x;
    const int rowBlk = blockIdx.y * BM;
    const int wid    = tid >> 5;
    const int lane   = tid & 31;
    const int warp_m = wid >> 2;          // 0..1 -> 16 rows each
    const int warp_n = wid & 3;
    const int mat    = lane >> 3;
    const int rin    = lane & 7;

    const int CHUNKS = K / 64;                       // 16

    uint32_t offA[4], offB[2][4];
    #pragma unroll
    for (int j = 0; j < 4; j++) {
        int row = warp_m * 16 + (mat & 1) * 8 + rin;
        int c   = 2 * j + (mat >> 1);
        offA[j] = row * 128 + ((c ^ (row & 7)) << 4);
    }
    #pragma unroll
    for (int bi = 0; bi < 2; bi++)
        #pragma unroll
        for (int j = 0; j < 4; j++) {
            int row = warp_n * 32 + bi * 16 + (mat >> 1) * 8 + rin;
            int c   = 2 * j + (mat & 1);
            offB[bi][j] = 2 * ABYTES + row * 128 + ((c ^ (row & 7)) << 4);
        }

    float acc[4][4];
    #pragma unroll
    for (int j = 0; j < 4; j++)
        #pragma unroll
        for (int q = 0; q < 4; q++) acc[j][q] = 0.0f;

    auto load_stage = [&](int s, int c) {
        int k0 = c * 64;
        uint32_t st = base + s * STAGE;
        {                                            // 32 rows x 8 chunks, both A
            int r = tid >> 3, cc = tid & 7;
            uint32_t sw = r * 128 + ((cc ^ (r & 7)) << 4);
            const char* srcH =
                (const char*)(Ahi + (size_t)(rowBlk + r) * K + k0) + cc * 16;
            const char* srcL =
                (const char*)(Alo + (size_t)(rowBlk + r) * K + k0) + cc * 16;
            CP16(st + sw, srcH);
            CP16(st + ABYTES + sw, srcL);
        }
        #pragma unroll
        for (int t = 0; t < 4; t++) {               // B: 128 rows (zfill > 95)
            int idx = tid + t * 256;
            int r = idx >> 3, cc = idx & 7;
            uint32_t sw = r * 128 + ((cc ^ (r & 7)) << 4);
            int ok = (r < XDBL_N);
            const char* src =
                (const char*)(Bhi + (size_t)(ok ? r : 0) * K + k0) + cc * 16;
            CP16Z(st + 2 * ABYTES + sw, src, ok ? 16u : 0u);
        }
    };

    #pragma unroll
    for (int s = 0; s < 3; s++) { load_stage(s, s); CP_COMMIT(); }

    int slot = 0;
    #pragma unroll 1
    for (int i = 0; i < CHUNKS; i++) {
        CP_WAIT2();
        __syncthreads();
        const uint32_t sb = base + slot * STAGE;
        #pragma unroll
        for (int pass = 0; pass < 2; pass++) {       // A-hi then A-lo, same B
            const uint32_t ab = sb + pass * ABYTES;
            #pragma unroll
            for (int j = 0; j < 4; j++) {
                uint32_t Af[4];
                ldsm4(Af, ab + offA[j]);
                uint32_t Bf[4][2];
                #pragma unroll
                for (int bi = 0; bi < 2; bi++) {
                    uint32_t r[4];
                    ldsm4(r, sb + offB[bi][j]);
                    Bf[bi * 2 + 0][0] = r[0]; Bf[bi * 2 + 0][1] = r[1];
                    Bf[bi * 2 + 1][0] = r[2]; Bf[bi * 2 + 1][1] = r[3];
                }
                #pragma unroll
                for (int ni = 0; ni < 4; ni++)
                    mma16816(acc[ni], Af, Bf[ni]);
            }
        }
        __syncthreads();
        if (i + 3 < CHUNKS) load_stage(slot, i + 3);
        CP_COMMIT();
        slot = (slot == 2) ? 0 : slot + 1;
    }

    // epilogue (N=96 bound check; dt split for cols [0,64))
    const int mrow = rowBlk + warp_m * 16 + (lane >> 2);
    const int ncol = warp_n * 32 + (lane & 3) * 2;
    #pragma unroll
    for (int ni = 0; ni < 4; ni++) {
        int n0 = ncol + ni * 8;
        if (n0 >= XDBL_N) continue;
        float v0 = acc[ni][0], v1 = acc[ni][1];
        float v2 = acc[ni][2], v3 = acc[ni][3];
        size_t r0 = (size_t)mrow * N + n0;
        size_t r1 = (size_t)(mrow + 8) * N + n0;
        *reinterpret_cast<float2*>(C + r0) = make_float2(v0, v1);
        *reinterpret_cast<float2*>(C + r1) = make_float2(v2, v3);
        if (n0 < DTRANK) {
            h16 hh, ll;
            size_t d0 = (size_t)mrow * DTRANK + n0;
            size_t d1 = (size_t)(mrow + 8) * DTRANK + n0;
            split_h16(v0, hh, ll); dth[d0] = hh;     dtl[d0] = ll;
            split_h16(v1, hh, ll); dth[d0 + 1] = hh; dtl[d0 + 1] = ll;
            split_h16(v2, hh, ll); dth[d1] = hh;     dtl[d1] = ll;
            split_h16(v3, hh, ll); dth[d1 + 1] = hh; dtl[d1 + 1] = ll;
        }
    }
}

// ---------------------------------------------------------------------------
// Combined prep — ONE launch: 4 weight transposes AND x -> fp16.
// ---------------------------------------------------------------------------
__global__ __launch_bounds__(256)
void prep_kernel(const float* __restrict__ W_in,
                 const float* __restrict__ W_xdbl,
                 const float* __restrict__ W_dt,
                 const float* __restrict__ W_out,
                 const float* __restrict__ x,
                 h16* __restrict__ b1h, h16* __restrict__ bxh,
                 h16* __restrict__ bdh,
                 h16* __restrict__ b2h, h16* __restrict__ a1h)
{
    int blk = blockIdx.x;
    if (blk >= 4256) {
        int i = (blk - 4256) * 1024 + threadIdx.x * 4;
        float4 v = *reinterpret_cast<const float4*>(x + i);
        __half2* ph = reinterpret_cast<__half2*>(a1h + i);
        ph[0] = __half2(__float2half_rn(v.x), __float2half_rn(v.y));
        ph[1] = __half2(__float2half_rn(v.z), __float2half_rn(v.w));
        return;
    }

    __shared__ float t[32][33];
    const float* in;
    h16 *oh;
    int R, C, bx, by;
    if (blk < 2048)      { in = W_in;   oh = b1h; R = 1024; C = 2048; bx = blk % 64; by = blk / 64; }
    else if (blk < 2144) { blk -= 2048; in = W_xdbl; oh = bxh; R = 1024; C = 96;   bx = blk % 3;  by = blk / 3; }
    else if (blk < 2208) { blk -= 2144; in = W_dt;  oh = bdh; R = 64; C = 1024; bx = blk % 32; by = blk / 32; }
    else                 { blk -= 2208; in = W_out; oh = b2h; R = 2048; C = 1024; bx = blk % 32; by = blk / 32; }

    const int cx = bx * 32, ry = by * 32;
    const int tx = threadIdx.x & 31, ty = threadIdx.x >> 5;   // 32 x 8
    #pragma unroll
    for (int j = ty; j < 32; j += 8)
        t[j][tx] = in[(size_t)(ry + j) * C + cx + tx];
    __syncthreads();
    #pragma unroll
    for (int j = ty; j < 32; j += 8) {
        float v = t[tx][j];
        size_t o = (size_t)(cx + j) * R + ry + tx;
        oh[o] = __float2half_rn(v);
    }
}

// ---------------------------------------------------------------------------
// Depthwise conv (k=4, SAME: pad left 1, right 2) + SiLU over BOTH halves,
// half2-vectorized: each thread handles 2 channels x 4 consecutive l outputs.
// ---------------------------------------------------------------------------
__global__ __launch_bounds__(256)
void conv_both_kernel(const h16* __restrict__ xz,
                      const float* __restrict__ wx, const float* __restrict__ bx,
                      const float* __restrict__ wz, const float* __restrict__ bz,
                      h16* __restrict__ xsh, h16* __restrict__ xsl,
                      h16* __restrict__ ch)
{
    const int half = blockIdx.y;
    const float* w    = half ? wz : wx;
    const float* bias = half ? bz : bx;
    const int col0 = half ? DHALF : 0;

    int idx = blockIdx.x * blockDim.x + threadIdx.x;   // < MROWS/4 * DHALF/2
    int c2  = (idx & 511) << 1;
    int bl4 = idx >> 9;
    int b   = bl4 >> 9;
    int l0  = (bl4 & 511) << 2;

    float2 w0 = *reinterpret_cast<const float2*>(w + c2);
    float2 w1 = *reinterpret_cast<const float2*>(w + DHALF + c2);
    float2 w2 = *reinterpret_cast<const float2*>(w + 2 * DHALF + c2);
    float2 w3 = *reinterpret_cast<const float2*>(w + 3 * DHALF + c2);
    float2 bv = *reinterpret_cast<const float2*>(bias + c2);

    const __half2* src = reinterpret_cast<const __half2*>(
        xz + (size_t)b * LSEQ * DINNER + col0 + c2);
    float2 win[7];
    #pragma unroll
    for (int j = 0; j < 7; j++) {
        int l = l0 + j - 1;
        win[j] = (l >= 0 && l < LSEQ)
                 ? __half22float2(src[(size_t)l * (DINNER / 2)])
                 : make_float2(0.0f, 0.0f);
    }

    #pragma unroll
    for (int k = 0; k < 4; k++) {
        float ax = bv.x, ay = bv.y;
        ax = fmaf(win[k].x,     w0.x, ax); ay = fmaf(win[k].y,     w0.y, ay);
        ax = fmaf(win[k + 1].x, w1.x, ax); ay = fmaf(win[k + 1].y, w1.y, ay);
        ax = fmaf(win[k + 2].x, w2.x, ax); ay = fmaf(win[k + 2].y, w2.y, ay);
        ax = fmaf(win[k + 3].x, w3.x, ax); ay = fmaf(win[k + 3].y, w3.y, ay);
        float vx = silu_f(ax), vy = silu_f(ay);
        size_t row = (size_t)b * LSEQ + l0 + k;
        if (half == 0) {
            h16 hx, lx, hy, ly;
            split_h16(vx, hx, lx); split_h16(vy, hy, ly);
            size_t o = row * DHALF + c2;
            *reinterpret_cast<__half2*>(xsh + o) = __half2(hx, hy);
            *reinterpret_cast<__half2*>(xsl + o) = __half2(lx, ly);
        } else {
            *reinterpret_cast<__half2*>(ch + row * DINNER + DHALF + c2) =
                __half2(__float2half_rn(vx), __float2half_rn(vy));
        }
    }
}

// ---------------------------------------------------------------------------
// Chunk-parallel selective scan.  A[d][n] = -(n+1) => dA_n = exp(-delta)^(n+1).
//   NCHUNK=32, LCHUNK=64 -> 1024 blocks in phases 1 and 3.
// u is read hi-only (fp16 rn).
// ---------------------------------------------------------------------------
#define PW16(p1, pw)                                                    \
    float p2 = (p1) * (p1), p3 = p2 * (p1), p4 = p2 * p2;               \
    float p5 = p4 * (p1), p6 = p4 * p2, p7 = p4 * p3, p8 = p4 * p4;     \
    float pw[16] = {(p1), p2, p3, p4, p5, p6, p7, p8,                   \
                    p8 * (p1), p8 * p2, p8 * p3, p8 * p4,               \
                    p8 * p5, p8 * p6, p8 * p7, p8 * p8};

__global__ __launch_bounds__(128)
void scan_p1(const float* __restrict__ delta,
             const h16* __restrict__ uh,
             const float* __restrict__ xdbl,
             float* __restrict__ q, float* __restrict__ S)
{
    const int tid = threadIdx.x;
    const int chunk = blockIdx.x, dblk = blockIdx.y, b = blockIdx.z;
    const int d = (dblk << 7) + tid;

    __shared__ float sB[16][DSTATE];
    __shared__ float sd[16][128];
    __shared__ float su[16][128];

    float h[DSTATE];
    #pragma unroll
    for (int n = 0; n < DSTATE; n++) h[n] = 0.0f;
    float sum = 0.0f;
    const size_t baseRow = (size_t)b * LSEQ + (size_t)chunk * LCHUNK;

    for (int t0 = 0; t0 < LCHUNK; t0 += 16) {
        {
            int s = tid >> 3;
            int i = (tid & 7) << 1;
            float2 v = *reinterpret_cast<const float2*>(
                xdbl + (baseRow + t0 + s) * XDBL_N + DTRANK + i);
            sB[s][i] = v.x; sB[s][i + 1] = v.y;
        }
        #pragma unroll
        for (int s = 0; s < 16; s++) {
            size_t r = (baseRow + t0 + s) * DHALF + d;
            sd[s][tid] = delta[r];
            su[s][tid] = __half2float(uh[r]);
        }
        __syncthreads();

        #pragma unroll
        for (int s = 0; s < 16; s++) {
            float dl = sd[s][tid];
            float du = dl * su[s][tid];
            sum += dl;
            float p1 = __expf(-dl);
            PW16(p1, pw)
            #pragma unroll
            for (int n = 0; n < DSTATE; n++)
                h[n] = fmaf(pw[n], h[n], du * sB[s][n]);
        }
        __syncthreads();
    }
    const size_t cbase = ((size_t)(b * NCHUNK + chunk) * DSTATE) * DHALF + d;
    #pragma unroll
    for (int n = 0; n < DSTATE; n++) q[cbase + (size_t)n * DHALF] = h[n];
    S[(size_t)(b * NCHUNK + chunk) * DHALF + d] = sum;
}

__global__ __launch_bounds__(128)
void scan_p2(const float* __restrict__ q, const float* __restrict__ S,
             float* __restrict__ hs)
{
    const int idx = blockIdx.x * 128 + threadIdx.x;   // < 4096
    const int b = idx >> 10, d = idx & (DHALF - 1);
    float h[DSTATE];
    #pragma unroll
    for (int n = 0; n < DSTATE; n++) h[n] = 0.0f;
    for (int c = 0; c < NCHUNK; c++) {
        const size_t cbase = ((size_t)(b * NCHUNK + c) * DSTATE) * DHALF + d;
        #pragma unroll
        for (int n = 0; n < DSTATE; n++) hs[cbase + (size_t)n * DHALF] = h[n];
        float s = S[(size_t)(b * NCHUNK + c) * DHALF + d];
        float p1 = __expf(-s);
        PW16(p1, pw)
        #pragma unroll
        for (int n = 0; n < DSTATE; n++)
            h[n] = fmaf(pw[n], h[n], q[cbase + (size_t)n * DHALF]);
    }
}

__global__ __launch_bounds__(128)
void scan_p3(const float* __restrict__ delta,
             const h16* __restrict__ uh,
             const float* __restrict__ xdbl, const float* __restrict__ hs,
             const float* __restrict__ Dv,
             h16* __restrict__ cat_h)
{
    const int tid = threadIdx.x;
    const int chunk = blockIdx.x, dblk = blockIdx.y, b = blockIdx.z;
    const int d = (dblk << 7) + tid;

    __shared__ float sB[16][DSTATE];
    __shared__ float sC[16][DSTATE];
    __shared__ float sd[16][128];
    __shared__ float su[16][128];

    float h[DSTATE];
    const size_t cbase = ((size_t)(b * NCHUNK + chunk) * DSTATE) * DHALF + d;
    #pragma unroll
    for (int n = 0; n < DSTATE; n++) h[n] = hs[cbase + (size_t)n * DHALF];
    const float Dd = Dv[d];
    const size_t baseRow = (size_t)b * LSEQ + (size_t)chunk * LCHUNK;

    for (int t0 = 0; t0 < LCHUNK; t0 += 16) {
        {
            int s = tid >> 3;
            int i = (tid & 7) << 2;
            float4 v = *reinterpret_cast<const float4*>(
                xdbl + (baseRow + t0 + s) * XDBL_N + DTRANK + i);
            float vv[4] = {v.x, v.y, v.z, v.w};
            #pragma unroll
            for (int qq = 0; qq < 4; qq++) {
                int ii = i + qq;
                if (ii < DSTATE) sB[s][ii] = vv[qq];
                else             sC[s][ii - DSTATE] = vv[qq];
            }
        }
        #pragma unroll
        for (int s = 0; s < 16; s++) {
            size_t r = (baseRow + t0 + s) * DHALF + d;
            sd[s][tid] = delta[r];
            su[s][tid] = __half2float(uh[r]);
        }
        __syncthreads();

        #pragma unroll
        for (int s = 0; s < 16; s++) {
            float dl = sd[s][tid];
            float uu = su[s][tid];
            float du = dl * uu;
            float p1 = __expf(-dl);
            PW16(p1, pw)
            float y0 = 0.f, y1 = 0.f, y2 = 0.f, y3 = 0.f;
            #pragma unroll
            for (int n = 0; n < DSTATE; n += 4) {
                h[n + 0] = fmaf(pw[n + 0], h[n + 0], du * sB[s][n + 0]);
                h[n + 1] = fmaf(pw[n + 1], h[n + 1], du * sB[s][n + 1]);
                h[n + 2] = fmaf(pw[n + 2], h[n + 2], du * sB[s][n + 2]);
                h[n + 3] = fmaf(pw[n + 3], h[n + 3], du * sB[s][n + 3]);
                y0 = fmaf(h[n + 0], sC[s][n + 0], y0);
                y1 = fmaf(h[n + 1], sC[s][n + 1], y1);
                y2 = fmaf(h[n + 2], sC[s][n + 2], y2);
                y3 = fmaf(h[n + 3], sC[s][n + 3], y3);
            }
            float yv = fmaf(uu, Dd, (y0 + y1) + (y2 + y3));
            cat_h[(baseRow + t0 + s) * DINNER + d] = __float2half_rn(yv);
        }
        __syncthreads();
    }
}

// ---------------------------------------------------------------------------
// Launch
// ---------------------------------------------------------------------------
extern "C" void kernel_launch(void* const* d_in, const int* in_sizes, int n_in,
                              void* d_out, int out_size)
{
    const float* x        = (const float*)d_in[0];
    const float* W_in     = (const float*)d_in[1];
    const float* conv_x_w = (const float*)d_in[2];
    const float* conv_x_b = (const float*)d_in[3];
    const float* conv_z_w = (const float*)d_in[4];
    const float* conv_z_b = (const float*)d_in[5];
    const float* W_xdbl   = (const float*)d_in[6];
    const float* W_dt     = (const float*)d_in[7];
    const float* inv_dt   = (const float*)d_in[8];
    const float* Dvec     = (const float*)d_in[9];
    const float* W_out    = (const float*)d_in[10];
    const float* b_out    = (const float*)d_in[11];
    float* out            = (float*)d_out;

    float *p_xdbl, *p_delta, *p_q, *p_hs, *p_S;
    h16 *p_xzh, *p_a1h, *p_b1h, *p_xsh, *p_xsl, *p_bxh;
    h16 *p_dth, *p_dtl, *p_bdh, *p_ch, *p_b2h;
    cudaGetSymbolAddress((void**)&p_xzh,   g_xzh);
    cudaGetSymbolAddress((void**)&p_xdbl,  g_xdbl);
    cudaGetSymbolAddress((void**)&p_delta, g_delta);
    cudaGetSymbolAddress((void**)&p_q,  g_q);
    cudaGetSymbolAddress((void**)&p_hs, g_hs);
    cudaGetSymbolAddress((void**)&p_S,  g_S);
    cudaGetSymbolAddress((void**)&p_a1h, g_a1h);
    cudaGetSymbolAddress((void**)&p_b1h, g_b1h);
    cudaGetSymbolAddress((void**)&p_xsh, g_xsh); cudaGetSymbolAddress((void**)&p_xsl, g_xsl);
    cudaGetSymbolAddress((void**)&p_bxh, g_bxh);
    cudaGetSymbolAddress((void**)&p_dth, g_dth); cudaGetSymbolAddress((void**)&p_dtl, g_dtl);
    cudaGetSymbolAddress((void**)&p_bdh, g_bdh);
    cudaGetSymbolAddress((void**)&p_ch,  g_ch);
    cudaGetSymbolAddress((void**)&p_b2h, g_b2h);

    constexpr int SMEM_128 = 3 * (128 * 128 + 128 * 128) + 1024;    // 99328
    constexpr int SMEM_SB  = 3 * (2 * 32 * 128 + 128 * 128) + 1024; // 74752
    cudaFuncSetAttribute((const void*)gemm_mma<128,1,false,false,true>,
                         cudaFuncAttributeMaxDynamicSharedMemorySize, SMEM_128);
    cudaFuncSetAttribute((const void*)gemm_mma<128,1,false,true,false>,
                         cudaFuncAttributeMaxDynamicSharedMemorySize, SMEM_128);
    cudaFuncSetAttribute((const void*)gemm_mma<128,2,true,true,false>,
                         cudaFuncAttributeMaxDynamicSharedMemorySize, SMEM_128);
    cudaFuncSetAttribute((const void*)gemm_xdbl_sb,
                         cudaFuncAttributeMaxDynamicSharedMemorySize, SMEM_SB);

    // 1) all prep in ONE launch: 4 weight transposes + x->fp16
    prep_kernel<<<4256 + 8192, 256>>>(W_in, W_xdbl, W_dt, W_out, x,
                                      p_b1h, p_bxh, p_bdh, p_b2h, p_a1h);

    // 2) xz = x @ W_in                              [8192,2048]  (1-stream, fp16 out)
    gemm_mma<128,1,false,false,true><<<dim3(DINNER / 128, MROWS / 128), 256, SMEM_128>>>(
        p_a1h, nullptr, p_b1h, nullptr, 0.0f, p_xzh, DINNER, DMODEL);

    // 3) both depthwise convs + silu (half2-vectorized, one launch)
    conv_both_kernel<<<dim3((MROWS / 4 * DHALF / 2) / 256, 2), 256>>>(
        p_xzh, conv_x_w, conv_x_b, conv_z_w, conv_z_b, p_xsh, p_xsl, p_ch);

    // 4) x_dbl = xs @ W_xdbl  [8192,96] (2-stream shared-B, BM=32 -> 256 CTAs)
    gemm_xdbl_sb<<<dim3(1, MROWS / 32), 256, SMEM_SB>>>(
        p_xsh, p_xsl, p_bxh, p_xdbl, p_dth, p_dtl);

    // 5) delta = softplus(dt_low @ W_dt + 2*inv_dt) [8192,1024]
    //    (2-stream: (dt_hi+dt_lo) @ W_dt_hi)
    gemm_mma<128,2,true,true,false><<<dim3(DHALF / 128, MROWS / 128), 256, SMEM_128>>>(
        p_dth, p_dtl, p_bdh, inv_dt, 2.0f, p_delta, DHALF, DTRANK);

    // 6) chunk-parallel selective scan (32 chunks) -> concat left half (fp16 rn)
    scan_p1<<<dim3(NCHUNK, 8, B_SZ), 128>>>(p_delta, p_xsh, p_xdbl, p_q, p_S);
    scan_p2<<<32, 128>>>(p_q, p_S, p_hs);
    scan_p3<<<dim3(NCHUNK, 8, B_SZ), 128>>>(p_delta, p_xsh, p_xdbl, p_hs, Dvec, p_ch);

    // 7) out = [y|z] @ W_out + b_out                [8192,1024]  (1-stream)
    gemm_mma<128,1,false,true,false><<<dim3(DMODEL / 128, MROWS / 128), 256, SMEM_128>>>(
        p_ch, nullptr, p_b2h, b_out, 1.0f, out, DMODEL, DINNER);
}